// round 6
// baseline (speedup 1.0000x reference)
#include <cuda_runtime.h>
#include <cuda_fp16.h>
#include <math_constants.h>
#include <cstdint>

#define CD 1024
#define ND 1024
#define OD 2048
#define KNN 20

// ---------------- scratch ----------------
__device__ float  g_xT[ND * CD];      // x^T (N, C) fp32, K-major
__device__ float  g_eT[ND * CD];      // eps^T (N, C) fp32
__device__ __half g_xh[ND * CD];      // fp16 split of x^T
__device__ __half g_xl[ND * CD];
__device__ __half g_wh[OD * CD];      // fp16 split of W
__device__ __half g_wl[OD * CD];
__device__ __half g_hh[ND * CD];      // fp16 split of h^T
__device__ __half g_hl[ND * CD];
__device__ float  g_gram[ND * ND];
__device__ float  g_x2[ND];
__device__ int    g_idx[ND * KNN];

// ---------------- helpers ----------------
__device__ __forceinline__ void split_h(float x, __half& h, __half& l) {
    h = __float2half_rn(x);
    l = __float2half_rn(x - __half2float(h));
}
__device__ __forceinline__ uint32_t pack2(__half a, __half b) {
    __half2 t = __halves2half2(a, b);
    return *(uint32_t*)&t;
}
__device__ __forceinline__ void mma_f16(float4& c, const uint32_t* a, const uint32_t* b) {
    asm volatile(
        "mma.sync.aligned.m16n8k16.row.col.f32.f16.f16.f32 "
        "{%0,%1,%2,%3}, {%4,%5,%6,%7}, {%8,%9}, {%0,%1,%2,%3};"
        : "+f"(c.x), "+f"(c.y), "+f"(c.z), "+f"(c.w)
        : "r"(a[0]), "r"(a[1]), "r"(a[2]), "r"(a[3]), "r"(b[0]), "r"(b[1]));
}

// ================= split-fp16 GEMM via mma.sync m16n8k16 =================
// D[M,N] = A[M,K]*B[N,K]^T, A = Ah+Al, B = Bh+Bl (pre-split fp16, K-major).
// 3 passes: Ah*Bh + Al*Bh + Ah*Bl. CTA 128 x NT, 128 threads (2x2 warps),
// warp tile 64 x NT/2. K chunk = 32 (2 k16 blocks).
//
// SMEM A packing: 16B unit(kb, rid, lq') holds rows {r, r+8} x ks
// {2lq, 2lq+1, 2lq+8, 2lq+9} (k rel. to kb*16), rid = (r>>4)*8 + (r&7),
// lq' = lq ^ ((r>>1)&3) (store-conflict swizzle). One lds.128 = full A frag.
// SMEM B packing: 8B unit(kb, lq, n) = {(n,2lq),(n,2lq+1),(n,2lq+8),(n,2lq+9)}.
// One lds.64 = full B frag. Row pad 4 units kills lq-stride conflicts.
template <int NT>
__global__ __launch_bounds__(128, 2)
void mma_gemm(const __half* __restrict__ Ah_, const __half* __restrict__ Al_,
              const __half* __restrict__ Bh_, const __half* __restrict__ Bl_,
              float* __restrict__ D, int ldd) {
    constexpr int BSTR = NT + 4;          // 8B units per (kb,lq) row
    constexpr int NTN  = NT / 16;         // n8 tiles per warp
    constexpr int BJ   = NT / 32;         // B load iterations

    __shared__ __half sAh[4096], sAl[4096];          // 2*64*4 units * 8 halves
    __shared__ __half sBh[32 * BSTR], sBl[32 * BSTR];

    const int t = threadIdx.x, wid = t >> 5, lane = t & 31;
    const int wm = (wid >> 1) * 64, wn = (wid & 1) * (NT / 2);
    const int lq = lane & 3, lg = lane >> 2;
    const int m0 = blockIdx.y * 128, n0 = blockIdx.x * NT;

    const uint4* pAh = (const uint4*)Ah_;
    const uint4* pAl = (const uint4*)Al_;
    const uint4* pBh = (const uint4*)Bh_;
    const uint4* pBl = (const uint4*)Bl_;

    float4 c[4][NTN];
#pragma unroll
    for (int mt = 0; mt < 4; mt++)
#pragma unroll
        for (int nt = 0; nt < NTN; nt++) c[mt][nt] = make_float4(0.f, 0.f, 0.f, 0.f);

    for (int i = 0; i < CD / 32; i++) {
        // ---- A: 128 rows x 32 k (512 uint4 loads) ----
#pragma unroll
        for (int j = 0; j < 4; j++) {
            int u = t + j * 128;
            int kgrp = u & 3, r = u >> 2;
            int kb = kgrp >> 1, khalf = kgrp & 1;
            int rid = ((r >> 4) << 3) + (r & 7);
            int rowhi = (r >> 3) & 1;
            int swz = (r >> 1) & 3;
            uint4 vh = pAh[(size_t)(m0 + r) * (CD / 8) + i * 4 + kgrp];
            uint4 vl = pAl[(size_t)(m0 + r) * (CD / 8) + i * 4 + kgrp];
            uint32_t* dh = (uint32_t*)sAh;
            uint32_t* dl = (uint32_t*)sAl;
            int ub = (kb * 64 + rid) * 4;
            int wo = khalf * 2 + rowhi;
            dh[(ub + (0 ^ swz)) * 4 + wo] = vh.x;
            dh[(ub + (1 ^ swz)) * 4 + wo] = vh.y;
            dh[(ub + (2 ^ swz)) * 4 + wo] = vh.z;
            dh[(ub + (3 ^ swz)) * 4 + wo] = vh.w;
            dl[(ub + (0 ^ swz)) * 4 + wo] = vl.x;
            dl[(ub + (1 ^ swz)) * 4 + wo] = vl.y;
            dl[(ub + (2 ^ swz)) * 4 + wo] = vl.z;
            dl[(ub + (3 ^ swz)) * 4 + wo] = vl.w;
        }
        // ---- B: NT rows x 32 k ----
#pragma unroll
        for (int j = 0; j < BJ; j++) {
            int u = t + j * 128;
            int kgrp = u & 3, n = u >> 2;
            int kb = kgrp >> 1, khalf = kgrp & 1;
            uint4 vh = pBh[(size_t)(n0 + n) * (CD / 8) + i * 4 + kgrp];
            uint4 vl = pBl[(size_t)(n0 + n) * (CD / 8) + i * 4 + kgrp];
            uint32_t* dh = (uint32_t*)sBh;
            uint32_t* dl = (uint32_t*)sBl;
            dh[((kb * 4 + 0) * BSTR + n) * 2 + khalf] = vh.x;
            dh[((kb * 4 + 1) * BSTR + n) * 2 + khalf] = vh.y;
            dh[((kb * 4 + 2) * BSTR + n) * 2 + khalf] = vh.z;
            dh[((kb * 4 + 3) * BSTR + n) * 2 + khalf] = vh.w;
            dl[((kb * 4 + 0) * BSTR + n) * 2 + khalf] = vl.x;
            dl[((kb * 4 + 1) * BSTR + n) * 2 + khalf] = vl.y;
            dl[((kb * 4 + 2) * BSTR + n) * 2 + khalf] = vl.z;
            dl[((kb * 4 + 3) * BSTR + n) * 2 + khalf] = vl.w;
        }
        __syncthreads();

        // ---- 3 split passes x 2 k16 blocks ----
#pragma unroll
        for (int pass = 0; pass < 3; pass++) {
            const uint32_t* A4 = (const uint32_t*)((pass == 1) ? sAl : sAh);
            const uint32_t* B2 = (const uint32_t*)((pass == 2) ? sBl : sBh);
#pragma unroll
            for (int kb = 0; kb < 2; kb++) {
                uint32_t a[4][4];
#pragma unroll
                for (int mt = 0; mt < 4; mt++) {
                    int mrow = (wm >> 4) + mt;
                    int unit = (kb * 64 + mrow * 8 + lg) * 4 + (lq ^ ((lg >> 1) & 3));
                    uint4 av = *(const uint4*)&A4[unit * 4];
                    a[mt][0] = av.x; a[mt][1] = av.y; a[mt][2] = av.z; a[mt][3] = av.w;
                }
                uint32_t b[NTN][2];
#pragma unroll
                for (int nt = 0; nt < NTN; nt++) {
                    int unit = (kb * 4 + lq) * BSTR + wn + nt * 8 + lg;
                    uint2 bv = *(const uint2*)&B2[unit * 2];
                    b[nt][0] = bv.x; b[nt][1] = bv.y;
                }
#pragma unroll
                for (int mt = 0; mt < 4; mt++)
#pragma unroll
                    for (int nt = 0; nt < NTN; nt++)
                        mma_f16(c[mt][nt], a[mt], b[nt]);
            }
        }
        __syncthreads();
    }

    // ---- epilogue ----
#pragma unroll
    for (int mt = 0; mt < 4; mt++) {
        int r0 = m0 + wm + mt * 16 + lg;
#pragma unroll
        for (int nt = 0; nt < NTN; nt++) {
            int cb = n0 + wn + nt * 8 + lq * 2;
            *(float2*)&D[(size_t)r0 * ldd + cb]       = make_float2(c[mt][nt].x, c[mt][nt].y);
            *(float2*)&D[(size_t)(r0 + 8) * ldd + cb] = make_float2(c[mt][nt].z, c[mt][nt].w);
        }
    }
}

// ================= transpose x, eps; emit fp32 + fp16-split x =================
__global__ __launch_bounds__(256) void transpose_kernel(
    const float* __restrict__ x, const float* __restrict__ e,
    float* __restrict__ xT, float* __restrict__ eT,
    __half* __restrict__ xh, __half* __restrict__ xl) {
    __shared__ float tx[32][33], te[32][33];
    const int i0 = blockIdx.x * 32;   // N
    const int j0 = blockIdx.y * 32;   // C
    const int c = threadIdx.x, r = threadIdx.y;
#pragma unroll
    for (int k = 0; k < 32; k += 8) {
        tx[r + k][c] = x[(size_t)(j0 + r + k) * ND + i0 + c];
        te[r + k][c] = e[(size_t)(j0 + r + k) * ND + i0 + c];
    }
    __syncthreads();
#pragma unroll
    for (int k = 0; k < 32; k += 8) {
        size_t o = (size_t)(i0 + r + k) * CD + j0 + c;
        float v = tx[c][r + k];
        xT[o] = v;
        eT[o] = te[c][r + k];
        __half h, l;
        split_h(v, h, l);
        xh[o] = h;
        xl[o] = l;
    }
}

// ================= W split =================
__global__ __launch_bounds__(256) void wsplit_kernel(const float* __restrict__ W,
                                                     __half* __restrict__ Wh,
                                                     __half* __restrict__ Wl) {
    int i = blockIdx.x * blockDim.x + threadIdx.x;   // over OD*CD/4
    float4 v = ((const float4*)W)[i];
    __half hx, lx, hy, ly, hz, lz, hw, lw;
    split_h(v.x, hx, lx); split_h(v.y, hy, ly);
    split_h(v.z, hz, lz); split_h(v.w, hw, lw);
    uint2 ph = make_uint2(pack2(hx, hy), pack2(hz, hw));
    uint2 pl = make_uint2(pack2(lx, ly), pack2(lz, lw));
    ((uint2*)Wh)[i] = ph;
    ((uint2*)Wl)[i] = pl;
}

// ================= diag =================
__global__ void diag_kernel(const float* __restrict__ G, float* __restrict__ x2) {
    int n = blockIdx.x * blockDim.x + threadIdx.x;
    if (n < ND) x2[n] = G[(size_t)n * ND + n];
}

// ================= top-20 (shuffle argmax) =================
__global__ __launch_bounds__(256) void topk_kernel(const float* __restrict__ G,
                                                   const float* __restrict__ x2,
                                                   int* __restrict__ idx) {
    __shared__ float d[ND];
    __shared__ float sv[8];
    __shared__ int   si[8];
    const int i = blockIdx.x;
    const int t = threadIdx.x;
    const int w = t >> 5, lane = t & 31;
    const float x2i = x2[i];

    for (int j = t; j < ND; j += 256)
        d[j] = 2.f * G[(size_t)i * ND + j] - x2i - x2[j];
    __syncthreads();

    for (int k = 0; k < KNN; k++) {
        float bv = -CUDART_INF_F;
        int   bi = ND;
#pragma unroll
        for (int u = 0; u < 4; u++) {
            int j = t + u * 256;
            float v = d[j];
            if (v > bv || (v == bv && j < bi)) { bv = v; bi = j; }
        }
#pragma unroll
        for (int off = 16; off > 0; off >>= 1) {
            float ov = __shfl_xor_sync(0xffffffffu, bv, off);
            int   oi = __shfl_xor_sync(0xffffffffu, bi, off);
            if (ov > bv || (ov == bv && oi < bi)) { bv = ov; bi = oi; }
        }
        if (lane == 0) { sv[w] = bv; si[w] = bi; }
        __syncthreads();
        if (w == 0) {
            float v2 = (lane < 8) ? sv[lane] : -CUDART_INF_F;
            int   i2 = (lane < 8) ? si[lane] : ND;
#pragma unroll
            for (int off = 4; off > 0; off >>= 1) {
                float ov = __shfl_xor_sync(0xffffffffu, v2, off);
                int   oi = __shfl_xor_sync(0xffffffffu, i2, off);
                if (ov > v2 || (ov == v2 && oi < i2)) { v2 = ov; i2 = oi; }
            }
            if (lane == 0) { idx[i * KNN + k] = i2; d[i2] = -CUDART_INF_F; }
        }
        __syncthreads();
    }
}

// ================= h^T = (1+eps)*x + neighbor-sum, emitted pre-split fp16 =====
__global__ __launch_bounds__(256) void hT_kernel(const float* __restrict__ xT,
                                                 const float* __restrict__ eT,
                                                 const int* __restrict__ idx,
                                                 __half* __restrict__ hh,
                                                 __half* __restrict__ hl) {
    __shared__ int nb[KNN];
    const int n = blockIdx.x;
    const int t = threadIdx.x;
    if (t < KNN) nb[t] = idx[n * KNN + t];
    __syncthreads();

    const size_t base = (size_t)n * CD + t * 4;
    float4 xv = *(const float4*)&xT[base];
    float4 ev = *(const float4*)&eT[base];
    float4 s;
    s.x = fmaf(ev.x, xv.x, xv.x);
    s.y = fmaf(ev.y, xv.y, xv.y);
    s.z = fmaf(ev.z, xv.z, xv.z);
    s.w = fmaf(ev.w, xv.w, xv.w);
#pragma unroll
    for (int k = 0; k < KNN; k++) {
        float4 nv = *(const float4*)&xT[(size_t)nb[k] * CD + t * 4];
        s.x += nv.x; s.y += nv.y; s.z += nv.z; s.w += nv.w;
    }
    __half hx, lx, hy, ly, hz, lz, hw, lw;
    split_h(s.x, hx, lx); split_h(s.y, hy, ly);
    split_h(s.z, hz, lz); split_h(s.w, hw, lw);
    ((uint2*)hh)[base / 4] = make_uint2(pack2(hx, hy), pack2(hz, hw));
    ((uint2*)hl)[base / 4] = make_uint2(pack2(lx, ly), pack2(lz, lw));
}

// ================= launch =================
extern "C" void kernel_launch(void* const* d_in, const int* in_sizes, int n_in,
                              void* d_out, int out_size) {
    const float* x   = (const float*)d_in[0];   // (C, N)
    const float* W   = (const float*)d_in[1];   // (O, C)
    const float* eps = (const float*)d_in[2];   // (C, N)
    float* out = (float*)d_out;                 // (O, N)

    float*  xT;   cudaGetSymbolAddress((void**)&xT,   g_xT);
    float*  eT;   cudaGetSymbolAddress((void**)&eT,   g_eT);
    __half* xh;   cudaGetSymbolAddress((void**)&xh,   g_xh);
    __half* xl;   cudaGetSymbolAddress((void**)&xl,   g_xl);
    __half* wh;   cudaGetSymbolAddress((void**)&wh,   g_wh);
    __half* wl;   cudaGetSymbolAddress((void**)&wl,   g_wl);
    __half* hh;   cudaGetSymbolAddress((void**)&hh,   g_hh);
    __half* hl;   cudaGetSymbolAddress((void**)&hl,   g_hl);
    float*  gram; cudaGetSymbolAddress((void**)&gram, g_gram);
    float*  x2;   cudaGetSymbolAddress((void**)&x2,   g_x2);
    int*    idx;  cudaGetSymbolAddress((void**)&idx,  g_idx);

    transpose_kernel<<<dim3(ND / 32, CD / 32), dim3(32, 8)>>>(x, eps, xT, eT, xh, xl);
    wsplit_kernel<<<(OD * CD / 4) / 256, 256>>>(W, wh, wl);
    // Gram: M=1024, N=1024, CTA 128x64 -> 128 CTAs
    mma_gemm<64><<<dim3(ND / 64, ND / 128), 128>>>(xh, xl, xh, xl, gram, ND);
    diag_kernel<<<ND / 256, 256>>>(gram, x2);
    topk_kernel<<<ND, 256>>>(gram, x2, idx);
    hT_kernel<<<ND, 256>>>(xT, eT, idx, hh, hl);
    // Out: M=2048, N=1024, CTA 128x128 -> 128 CTAs
    mma_gemm<128><<<dim3(ND / 128, OD / 128), 128>>>(wh, wl, hh, hl, out, ND);
}

// round 7
// speedup vs baseline: 1.4825x; 1.4825x over previous
#include <cuda_runtime.h>
#include <cuda_fp16.h>
#include <math_constants.h>
#include <cstdint>

#define CD 1024
#define ND 1024
#define OD 2048
#define KNN 20

// ---------------- scratch ----------------
__device__ float  g_xT[ND * CD];      // x^T (N, C) fp32, K-major
__device__ float  g_eT[ND * CD];      // eps^T (N, C) fp32
__device__ __half g_xh[ND * CD];      // fp16 split of x^T
__device__ __half g_xl[ND * CD];
__device__ __half g_wh[OD * CD];      // fp16 split of W
__device__ __half g_wl[OD * CD];
__device__ __half g_hh[ND * CD];      // fp16 split of h^T
__device__ __half g_hl[ND * CD];
__device__ float  g_gram[ND * ND];
__device__ float  g_x2[ND];
__device__ int    g_idx[ND * KNN];

// ---------------- helpers ----------------
__device__ __forceinline__ void split_h(float x, __half& h, __half& l) {
    h = __float2half_rn(x);
    l = __float2half_rn(x - __half2float(h));
}
__device__ __forceinline__ uint32_t pack2(__half a, __half b) {
    __half2 t = __halves2half2(a, b);
    return *(uint32_t*)&t;
}
__device__ __forceinline__ void mma_f16(float4& c, const uint32_t* a, const uint32_t* b) {
    asm volatile(
        "mma.sync.aligned.m16n8k16.row.col.f32.f16.f16.f32 "
        "{%0,%1,%2,%3}, {%4,%5,%6,%7}, {%8,%9}, {%0,%1,%2,%3};"
        : "+f"(c.x), "+f"(c.y), "+f"(c.z), "+f"(c.w)
        : "r"(a[0]), "r"(a[1]), "r"(a[2]), "r"(a[3]), "r"(b[0]), "r"(b[1]));
}

// ================= split-fp16 GEMM via mma.sync m16n8k16 =================
// D[M,N] = A[M,K]*B[N,K]^T, A = Ah+Al, B = Bh+Bl (pre-split fp16, K-major).
// 3 passes: Ah*Bh + Al*Bh + Ah*Bl. CTA 128 x NT, 128 threads (2x2 warps),
// warp tile 64 x NT/2. K chunk = 32 (2 k16 blocks).
//
// SMEM A packing: 16B unit(kb, rid, lq') holds rows {r, r+8} x ks
// {2lq, 2lq+1, 2lq+8, 2lq+9} (k rel. to kb*16), rid = (r>>4)*8 + (r&7),
// lq' = lq ^ ((r>>1)&3) (store-conflict swizzle). One lds.128 = full A frag.
// SMEM B packing: 8B unit(kb, lq, n) = {(n,2lq),(n,2lq+1),(n,2lq+8),(n,2lq+9)}.
// One lds.64 = full B frag. Row pad 4 units kills lq-stride conflicts.
template <int NT>
__global__ __launch_bounds__(128, 2)
void mma_gemm(const __half* __restrict__ Ah_, const __half* __restrict__ Al_,
              const __half* __restrict__ Bh_, const __half* __restrict__ Bl_,
              float* __restrict__ D, int ldd) {
    constexpr int BSTR = NT + 4;          // 8B units per (kb,lq) row
    constexpr int NTN  = NT / 16;         // n8 tiles per warp
    constexpr int BJ   = NT / 32;         // B load iterations

    __shared__ __half sAh[4096], sAl[4096];          // 2*64*4 units * 8 halves
    __shared__ __half sBh[32 * BSTR], sBl[32 * BSTR];

    const int t = threadIdx.x, wid = t >> 5, lane = t & 31;
    const int wm = (wid >> 1) * 64, wn = (wid & 1) * (NT / 2);
    const int lq = lane & 3, lg = lane >> 2;
    const int m0 = blockIdx.y * 128, n0 = blockIdx.x * NT;

    const uint4* pAh = (const uint4*)Ah_;
    const uint4* pAl = (const uint4*)Al_;
    const uint4* pBh = (const uint4*)Bh_;
    const uint4* pBl = (const uint4*)Bl_;

    float4 c[4][NTN];
#pragma unroll
    for (int mt = 0; mt < 4; mt++)
#pragma unroll
        for (int nt = 0; nt < NTN; nt++) c[mt][nt] = make_float4(0.f, 0.f, 0.f, 0.f);

    for (int i = 0; i < CD / 32; i++) {
        // ---- A: 128 rows x 32 k (512 uint4 loads) ----
#pragma unroll
        for (int j = 0; j < 4; j++) {
            int u = t + j * 128;
            int kgrp = u & 3, r = u >> 2;
            int kb = kgrp >> 1, khalf = kgrp & 1;
            int rid = ((r >> 4) << 3) + (r & 7);
            int rowhi = (r >> 3) & 1;
            int swz = (r >> 1) & 3;
            uint4 vh = pAh[(size_t)(m0 + r) * (CD / 8) + i * 4 + kgrp];
            uint4 vl = pAl[(size_t)(m0 + r) * (CD / 8) + i * 4 + kgrp];
            uint32_t* dh = (uint32_t*)sAh;
            uint32_t* dl = (uint32_t*)sAl;
            int ub = (kb * 64 + rid) * 4;
            int wo = khalf * 2 + rowhi;
            dh[(ub + (0 ^ swz)) * 4 + wo] = vh.x;
            dh[(ub + (1 ^ swz)) * 4 + wo] = vh.y;
            dh[(ub + (2 ^ swz)) * 4 + wo] = vh.z;
            dh[(ub + (3 ^ swz)) * 4 + wo] = vh.w;
            dl[(ub + (0 ^ swz)) * 4 + wo] = vl.x;
            dl[(ub + (1 ^ swz)) * 4 + wo] = vl.y;
            dl[(ub + (2 ^ swz)) * 4 + wo] = vl.z;
            dl[(ub + (3 ^ swz)) * 4 + wo] = vl.w;
        }
        // ---- B: NT rows x 32 k ----
#pragma unroll
        for (int j = 0; j < BJ; j++) {
            int u = t + j * 128;
            int kgrp = u & 3, n = u >> 2;
            int kb = kgrp >> 1, khalf = kgrp & 1;
            uint4 vh = pBh[(size_t)(n0 + n) * (CD / 8) + i * 4 + kgrp];
            uint4 vl = pBl[(size_t)(n0 + n) * (CD / 8) + i * 4 + kgrp];
            uint32_t* dh = (uint32_t*)sBh;
            uint32_t* dl = (uint32_t*)sBl;
            dh[((kb * 4 + 0) * BSTR + n) * 2 + khalf] = vh.x;
            dh[((kb * 4 + 1) * BSTR + n) * 2 + khalf] = vh.y;
            dh[((kb * 4 + 2) * BSTR + n) * 2 + khalf] = vh.z;
            dh[((kb * 4 + 3) * BSTR + n) * 2 + khalf] = vh.w;
            dl[((kb * 4 + 0) * BSTR + n) * 2 + khalf] = vl.x;
            dl[((kb * 4 + 1) * BSTR + n) * 2 + khalf] = vl.y;
            dl[((kb * 4 + 2) * BSTR + n) * 2 + khalf] = vl.z;
            dl[((kb * 4 + 3) * BSTR + n) * 2 + khalf] = vl.w;
        }
        __syncthreads();

        // ---- 3 split passes x 2 k16 blocks ----
#pragma unroll
        for (int pass = 0; pass < 3; pass++) {
            const uint32_t* A4 = (const uint32_t*)((pass == 1) ? sAl : sAh);
            const uint32_t* B2 = (const uint32_t*)((pass == 2) ? sBl : sBh);
#pragma unroll
            for (int kb = 0; kb < 2; kb++) {
                uint32_t a[4][4];
#pragma unroll
                for (int mt = 0; mt < 4; mt++) {
                    int mrow = (wm >> 4) + mt;
                    int unit = (kb * 64 + mrow * 8 + lg) * 4 + (lq ^ ((lg >> 1) & 3));
                    uint4 av = *(const uint4*)&A4[unit * 4];
                    a[mt][0] = av.x; a[mt][1] = av.y; a[mt][2] = av.z; a[mt][3] = av.w;
                }
                uint32_t b[NTN][2];
#pragma unroll
                for (int nt = 0; nt < NTN; nt++) {
                    int unit = (kb * 4 + lq) * BSTR + wn + nt * 8 + lg;
                    uint2 bv = *(const uint2*)&B2[unit * 2];
                    b[nt][0] = bv.x; b[nt][1] = bv.y;
                }
#pragma unroll
                for (int mt = 0; mt < 4; mt++)
#pragma unroll
                    for (int nt = 0; nt < NTN; nt++)
                        mma_f16(c[mt][nt], a[mt], b[nt]);
            }
        }
        __syncthreads();
    }

    // ---- epilogue ----
#pragma unroll
    for (int mt = 0; mt < 4; mt++) {
        int r0 = m0 + wm + mt * 16 + lg;
#pragma unroll
        for (int nt = 0; nt < NTN; nt++) {
            int cb = n0 + wn + nt * 8 + lq * 2;
            *(float2*)&D[(size_t)r0 * ldd + cb]       = make_float2(c[mt][nt].x, c[mt][nt].y);
            *(float2*)&D[(size_t)(r0 + 8) * ldd + cb] = make_float2(c[mt][nt].z, c[mt][nt].w);
        }
    }
}

// ================= transpose x, eps; emit fp32 + fp16-split x =================
__global__ __launch_bounds__(256) void transpose_kernel(
    const float* __restrict__ x, const float* __restrict__ e,
    float* __restrict__ xT, float* __restrict__ eT,
    __half* __restrict__ xh, __half* __restrict__ xl) {
    __shared__ float tx[32][33], te[32][33];
    const int i0 = blockIdx.x * 32;   // N
    const int j0 = blockIdx.y * 32;   // C
    const int c = threadIdx.x, r = threadIdx.y;
#pragma unroll
    for (int k = 0; k < 32; k += 8) {
        tx[r + k][c] = x[(size_t)(j0 + r + k) * ND + i0 + c];
        te[r + k][c] = e[(size_t)(j0 + r + k) * ND + i0 + c];
    }
    __syncthreads();
#pragma unroll
    for (int k = 0; k < 32; k += 8) {
        size_t o = (size_t)(i0 + r + k) * CD + j0 + c;
        float v = tx[c][r + k];
        xT[o] = v;
        eT[o] = te[c][r + k];
        __half h, l;
        split_h(v, h, l);
        xh[o] = h;
        xl[o] = l;
    }
}

// ================= W split =================
__global__ __launch_bounds__(256) void wsplit_kernel(const float* __restrict__ W,
                                                     __half* __restrict__ Wh,
                                                     __half* __restrict__ Wl) {
    int i = blockIdx.x * blockDim.x + threadIdx.x;   // over OD*CD/4
    float4 v = ((const float4*)W)[i];
    __half hx, lx, hy, ly, hz, lz, hw, lw;
    split_h(v.x, hx, lx); split_h(v.y, hy, ly);
    split_h(v.z, hz, lz); split_h(v.w, hw, lw);
    uint2 ph = make_uint2(pack2(hx, hy), pack2(hz, hw));
    uint2 pl = make_uint2(pack2(lx, ly), pack2(lz, lw));
    ((uint2*)Wh)[i] = ph;
    ((uint2*)Wl)[i] = pl;
}

// ================= diag =================
__global__ void diag_kernel(const float* __restrict__ G, float* __restrict__ x2) {
    int n = blockIdx.x * blockDim.x + threadIdx.x;
    if (n < ND) x2[n] = G[(size_t)n * ND + n];
}

// ================= top-20 (shuffle argmax) =================
__global__ __launch_bounds__(256) void topk_kernel(const float* __restrict__ G,
                                                   const float* __restrict__ x2,
                                                   int* __restrict__ idx) {
    __shared__ float d[ND];
    __shared__ float sv[8];
    __shared__ int   si[8];
    const int i = blockIdx.x;
    const int t = threadIdx.x;
    const int w = t >> 5, lane = t & 31;
    const float x2i = x2[i];

    for (int j = t; j < ND; j += 256)
        d[j] = 2.f * G[(size_t)i * ND + j] - x2i - x2[j];
    __syncthreads();

    for (int k = 0; k < KNN; k++) {
        float bv = -CUDART_INF_F;
        int   bi = ND;
#pragma unroll
        for (int u = 0; u < 4; u++) {
            int j = t + u * 256;
            float v = d[j];
            if (v > bv || (v == bv && j < bi)) { bv = v; bi = j; }
        }
#pragma unroll
        for (int off = 16; off > 0; off >>= 1) {
            float ov = __shfl_xor_sync(0xffffffffu, bv, off);
            int   oi = __shfl_xor_sync(0xffffffffu, bi, off);
            if (ov > bv || (ov == bv && oi < bi)) { bv = ov; bi = oi; }
        }
        if (lane == 0) { sv[w] = bv; si[w] = bi; }
        __syncthreads();
        if (w == 0) {
            float v2 = (lane < 8) ? sv[lane] : -CUDART_INF_F;
            int   i2 = (lane < 8) ? si[lane] : ND;
#pragma unroll
            for (int off = 4; off > 0; off >>= 1) {
                float ov = __shfl_xor_sync(0xffffffffu, v2, off);
                int   oi = __shfl_xor_sync(0xffffffffu, i2, off);
                if (ov > v2 || (ov == v2 && oi < i2)) { v2 = ov; i2 = oi; }
            }
            if (lane == 0) { idx[i * KNN + k] = i2; d[i2] = -CUDART_INF_F; }
        }
        __syncthreads();
    }
}

// ================= h^T = (1+eps)*x + neighbor-sum, emitted pre-split fp16 =====
__global__ __launch_bounds__(256) void hT_kernel(const float* __restrict__ xT,
                                                 const float* __restrict__ eT,
                                                 const int* __restrict__ idx,
                                                 __half* __restrict__ hh,
                                                 __half* __restrict__ hl) {
    __shared__ int nb[KNN];
    const int n = blockIdx.x;
    const int t = threadIdx.x;
    if (t < KNN) nb[t] = idx[n * KNN + t];
    __syncthreads();

    const size_t base = (size_t)n * CD + t * 4;
    float4 xv = *(const float4*)&xT[base];
    float4 ev = *(const float4*)&eT[base];
    float4 s;
    s.x = fmaf(ev.x, xv.x, xv.x);
    s.y = fmaf(ev.y, xv.y, xv.y);
    s.z = fmaf(ev.z, xv.z, xv.z);
    s.w = fmaf(ev.w, xv.w, xv.w);
#pragma unroll
    for (int k = 0; k < KNN; k++) {
        float4 nv = *(const float4*)&xT[(size_t)nb[k] * CD + t * 4];
        s.x += nv.x; s.y += nv.y; s.z += nv.z; s.w += nv.w;
    }
    __half hx, lx, hy, ly, hz, lz, hw, lw;
    split_h(s.x, hx, lx); split_h(s.y, hy, ly);
    split_h(s.z, hz, lz); split_h(s.w, hw, lw);
    ((uint2*)hh)[base / 4] = make_uint2(pack2(hx, hy), pack2(hz, hw));
    ((uint2*)hl)[base / 4] = make_uint2(pack2(lx, ly), pack2(lz, lw));
}

// ================= launch =================
extern "C" void kernel_launch(void* const* d_in, const int* in_sizes, int n_in,
                              void* d_out, int out_size) {
    const float* x   = (const float*)d_in[0];   // (C, N)
    const float* W   = (const float*)d_in[1];   // (O, C)
    const float* eps = (const float*)d_in[2];   // (C, N)
    float* out = (float*)d_out;                 // (O, N)

    float*  xT;   cudaGetSymbolAddress((void**)&xT,   g_xT);
    float*  eT;   cudaGetSymbolAddress((void**)&eT,   g_eT);
    __half* xh;   cudaGetSymbolAddress((void**)&xh,   g_xh);
    __half* xl;   cudaGetSymbolAddress((void**)&xl,   g_xl);
    __half* wh;   cudaGetSymbolAddress((void**)&wh,   g_wh);
    __half* wl;   cudaGetSymbolAddress((void**)&wl,   g_wl);
    __half* hh;   cudaGetSymbolAddress((void**)&hh,   g_hh);
    __half* hl;   cudaGetSymbolAddress((void**)&hl,   g_hl);
    float*  gram; cudaGetSymbolAddress((void**)&gram, g_gram);
    float*  x2;   cudaGetSymbolAddress((void**)&x2,   g_x2);
    int*    idx;  cudaGetSymbolAddress((void**)&idx,  g_idx);

    transpose_kernel<<<dim3(ND / 32, CD / 32), dim3(32, 8)>>>(x, eps, xT, eT, xh, xl);
    wsplit_kernel<<<(OD * CD / 4) / 256, 256>>>(W, wh, wl);
    // Gram: M=1024, N=1024, CTA 128x64 -> 128 CTAs
    mma_gemm<64><<<dim3(ND / 64, ND / 128), 128>>>(xh, xl, xh, xl, gram, ND);
    diag_kernel<<<ND / 256, 256>>>(gram, x2);
    topk_kernel<<<ND, 256>>>(gram, x2, idx);
    hT_kernel<<<ND, 256>>>(xT, eT, idx, hh, hl);
    // Out: M=2048, N=1024, CTA 128x128 -> 128 CTAs
    mma_gemm<128><<<dim3(ND / 128, OD / 128), 128>>>(wh, wl, hh, hl, out, ND);
}

// round 8
// speedup vs baseline: 2.1653x; 1.4606x over previous
#include <cuda_runtime.h>
#include <cuda_fp16.h>
#include <math_constants.h>
#include <cstdint>

#define CD 1024
#define ND 1024
#define OD 2048
#define KNN 20

// ---------------- scratch ----------------
__device__ __align__(16) float  g_xT[ND * CD];
__device__ __align__(16) float  g_eT[ND * CD];
__device__ __align__(16) __half g_xh[ND * CD];
__device__ __align__(16) __half g_xl[ND * CD];
__device__ __align__(16) __half g_wh[OD * CD];
__device__ __align__(16) __half g_wl[OD * CD];
__device__ __align__(16) __half g_hh[ND * CD];
__device__ __align__(16) __half g_hl[ND * CD];
__device__ __align__(16) float  g_gram[ND * ND];
__device__ __align__(16) float  g_x2[ND];
__device__            int    g_idx[ND * KNN];

// ---------------- helpers ----------------
__device__ __forceinline__ void split_h(float x, __half& h, __half& l) {
    h = __float2half_rn(x);
    l = __float2half_rn(x - __half2float(h));
}
__device__ __forceinline__ uint32_t pack2(__half a, __half b) {
    __half2 t = __halves2half2(a, b);
    return *(uint32_t*)&t;
}
__device__ __forceinline__ uint32_t s2u(const void* p) {
    uint32_t a;
    asm("{ .reg .u64 t; cvta.to.shared.u64 t, %1; cvt.u32.u64 %0, t; }" : "=r"(a) : "l"(p));
    return a;
}
__device__ __forceinline__ void cp16(uint32_t s, const void* g) {
    asm volatile("cp.async.cg.shared.global [%0], [%1], 16;" :: "r"(s), "l"(g));
}
#define CP_COMMIT() asm volatile("cp.async.commit_group;" ::: "memory")
#define CP_WAIT(n)  asm volatile("cp.async.wait_group %0;" :: "n"(n) : "memory")

__device__ __forceinline__ void ldm_x4(uint32_t* r, uint32_t addr) {
    asm volatile("ldmatrix.sync.aligned.m8n8.x4.shared.b16 {%0,%1,%2,%3}, [%4];"
                 : "=r"(r[0]), "=r"(r[1]), "=r"(r[2]), "=r"(r[3]) : "r"(addr));
}
__device__ __forceinline__ void ldm_x2(uint32_t* r, uint32_t addr) {
    asm volatile("ldmatrix.sync.aligned.m8n8.x2.shared.b16 {%0,%1}, [%2];"
                 : "=r"(r[0]), "=r"(r[1]) : "r"(addr));
}
__device__ __forceinline__ void mma_f16(float4& c, const uint32_t* a, const uint32_t* b) {
    asm volatile(
        "mma.sync.aligned.m16n8k16.row.col.f32.f16.f16.f32 "
        "{%0,%1,%2,%3}, {%4,%5,%6,%7}, {%8,%9}, {%0,%1,%2,%3};"
        : "+f"(c.x), "+f"(c.y), "+f"(c.z), "+f"(c.w)
        : "r"(a[0]), "r"(a[1]), "r"(a[2]), "r"(a[3]), "r"(b[0]), "r"(b[1]));
}
// swizzled byte offset for row r (64B rows), 16B chunk c
__device__ __forceinline__ uint32_t swoff(int r, int c) {
    return (uint32_t)(r * 64 + ((c ^ ((r >> 1) & 3)) << 4));
}

// ================= split-fp16 GEMM: cp.async x3 stages + ldmatrix ============
// D[M,N] = (Ah+Al)[M,K] * (Bh+Bl)[N,K]^T, 3 passes (hh, lh, hl).
// CTA 128 x NT, 128 thr (2x2 warps), warp 64 x NT/2. K-chunk 32 halves.
// SMEM stage: [Ah 128x32 | Al | Bh NTx32 | Bl], 64B rows, XOR-swizzled chunks.
template <int NT>
__global__ __launch_bounds__(128, 2)
void mma_gemm(const __half* __restrict__ Ah_, const __half* __restrict__ Al_,
              const __half* __restrict__ Bh_, const __half* __restrict__ Bl_,
              float* __restrict__ D, int ldd, float* __restrict__ X2) {
    constexpr int NTN   = NT / 16;
    constexpr int ABY   = 128 * 64;            // bytes per A split (8192)
    constexpr int BOFF  = 2 * ABY;             // B region offset
    constexpr int BBY   = NT * 64;             // bytes per B split
    constexpr int STAGE = BOFF + 2 * BBY;      // stage bytes
    constexpr int NI    = CD / 32;

    extern __shared__ char smem[];
    const uint32_t smb = s2u(smem);

    const int t = threadIdx.x, wid = t >> 5, lane = t & 31;
    const int wm = (wid >> 1) * 64, wn = (wid & 1) * (NT / 2);
    const int lq = lane & 3, lg = lane >> 2;
    const int m0 = blockIdx.y * 128, n0 = blockIdx.x * NT;

    const int rA = t >> 2, cA = t & 3;         // thread's (row,chunk) for loads

    auto load_stage = [&](int chunk, int st) {
        const uint32_t sb = smb + st * STAGE;
        const size_t kofs = (size_t)chunk * 32;
#pragma unroll
        for (int j = 0; j < 4; j++) {
            int r = rA + j * 32;
            uint32_t dst = sb + swoff(r, cA);
            const size_t go = (size_t)(m0 + r) * CD + kofs + cA * 8;
            cp16(dst,       Ah_ + go);
            cp16(dst + ABY, Al_ + go);
        }
#pragma unroll
        for (int j = 0; j < NT / 32; j++) {
            int r = rA + j * 32;
            uint32_t dst = sb + BOFF + swoff(r, cA);
            const size_t go = (size_t)(n0 + r) * CD + kofs + cA * 8;
            cp16(dst,       Bh_ + go);
            cp16(dst + BBY, Bl_ + go);
        }
    };

    float4 c[4][NTN];
#pragma unroll
    for (int mt = 0; mt < 4; mt++)
#pragma unroll
        for (int nt = 0; nt < NTN; nt++) c[mt][nt] = make_float4(0.f, 0.f, 0.f, 0.f);

    // prologue: stages 0,1
    load_stage(0, 0); CP_COMMIT();
    load_stage(1, 1); CP_COMMIT();

    for (int i = 0; i < NI; i++) {
        CP_WAIT(1);
        __syncthreads();
        const int nf = i + 2;
        if (nf < NI) load_stage(nf, nf % 3);
        CP_COMMIT();

        const uint32_t sb = smb + (i % 3) * STAGE;
#pragma unroll
        for (int pass = 0; pass < 3; pass++) {
            const uint32_t ab = sb + ((pass == 1) ? ABY : 0);
            const uint32_t bb = sb + BOFF + ((pass == 2) ? BBY : 0);
#pragma unroll
            for (int kb = 0; kb < 2; kb++) {
                uint32_t a[4][4];
#pragma unroll
                for (int mt = 0; mt < 4; mt++) {
                    int row = wm + mt * 16 + (lane & 15);
                    ldm_x4(a[mt], ab + swoff(row, 2 * kb + (lane >> 4)));
                }
                uint32_t b[NTN][2];
#pragma unroll
                for (int nt = 0; nt < NTN; nt++) {
                    int row = wn + nt * 8 + (lane & 7);
                    ldm_x2(b[nt], bb + swoff(row, 2 * kb + ((lane >> 3) & 1)));
                }
#pragma unroll
                for (int mt = 0; mt < 4; mt++)
#pragma unroll
                    for (int nt = 0; nt < NTN; nt++)
                        mma_f16(c[mt][nt], a[mt], b[nt]);
            }
        }
        __syncthreads();
    }

    // ---- epilogue (+ fused diag extraction for the Gram call) ----
#pragma unroll
    for (int mt = 0; mt < 4; mt++) {
        int r0 = m0 + wm + mt * 16 + lg;
#pragma unroll
        for (int nt = 0; nt < NTN; nt++) {
            int cb = n0 + wn + nt * 8 + lq * 2;
            *(float2*)&D[(size_t)r0 * ldd + cb]       = make_float2(c[mt][nt].x, c[mt][nt].y);
            *(float2*)&D[(size_t)(r0 + 8) * ldd + cb] = make_float2(c[mt][nt].z, c[mt][nt].w);
            if (X2) {
                if (r0 == cb)          X2[r0] = c[mt][nt].x;
                else if (r0 == cb + 1) X2[r0] = c[mt][nt].y;
                if (r0 + 8 == cb)          X2[r0 + 8] = c[mt][nt].z;
                else if (r0 + 8 == cb + 1) X2[r0 + 8] = c[mt][nt].w;
            }
        }
    }
}

// ================= transpose x, eps; emit fp32 + fp16-split x =================
__global__ __launch_bounds__(256) void transpose_kernel(
    const float* __restrict__ x, const float* __restrict__ e,
    float* __restrict__ xT, float* __restrict__ eT,
    __half* __restrict__ xh, __half* __restrict__ xl) {
    __shared__ float tx[32][33], te[32][33];
    const int i0 = blockIdx.x * 32;   // N
    const int j0 = blockIdx.y * 32;   // C
    const int c = threadIdx.x, r = threadIdx.y;
#pragma unroll
    for (int k = 0; k < 32; k += 8) {
        tx[r + k][c] = x[(size_t)(j0 + r + k) * ND + i0 + c];
        te[r + k][c] = e[(size_t)(j0 + r + k) * ND + i0 + c];
    }
    __syncthreads();
#pragma unroll
    for (int k = 0; k < 32; k += 8) {
        size_t o = (size_t)(i0 + r + k) * CD + j0 + c;
        float v = tx[c][r + k];
        xT[o] = v;
        eT[o] = te[c][r + k];
        __half h, l;
        split_h(v, h, l);
        xh[o] = h;
        xl[o] = l;
    }
}

// ================= W split =================
__global__ __launch_bounds__(256) void wsplit_kernel(const float* __restrict__ W,
                                                     __half* __restrict__ Wh,
                                                     __half* __restrict__ Wl) {
    int i = blockIdx.x * blockDim.x + threadIdx.x;   // over OD*CD/4
    float4 v = ((const float4*)W)[i];
    __half hx, lx, hy, ly, hz, lz, hw, lw;
    split_h(v.x, hx, lx); split_h(v.y, hy, ly);
    split_h(v.z, hz, lz); split_h(v.w, hw, lw);
    ((uint2*)Wh)[i] = make_uint2(pack2(hx, hy), pack2(hz, hw));
    ((uint2*)Wl)[i] = make_uint2(pack2(lx, ly), pack2(lz, lw));
}

// ================= top-20: tournament argmax, barrier-free loop =================
__global__ __launch_bounds__(256) void topk_kernel(const float* __restrict__ G,
                                                   const float* __restrict__ x2,
                                                   int* __restrict__ idx) {
    __shared__ float d[ND];
    __shared__ float m1v[256];
    __shared__ int   m1i[256];
    const int i = blockIdx.x, t = threadIdx.x;
    const float x2i = x2[i];

    float4 g = *(const float4*)&G[(size_t)i * ND + t * 4];
    float4 q = *(const float4*)&x2[t * 4];
    float v0 = 2.f * g.x - x2i - q.x;
    float v1 = 2.f * g.y - x2i - q.y;
    float v2 = 2.f * g.z - x2i - q.z;
    float v3 = 2.f * g.w - x2i - q.w;
    *(float4*)&d[t * 4] = make_float4(v0, v1, v2, v3);
    float bv = v0; int bi = t * 4;
    if (v1 > bv) { bv = v1; bi = t * 4 + 1; }
    if (v2 > bv) { bv = v2; bi = t * 4 + 2; }
    if (v3 > bv) { bv = v3; bi = t * 4 + 3; }
    m1v[t] = bv; m1i[t] = bi;
    __syncthreads();

    if (t < 32) {
        const int lane = t;
        for (int k = 0; k < KNN; k++) {
            float cv = -CUDART_INF_F; int ci = 1 << 30;
#pragma unroll
            for (int e = 0; e < 8; e++) {
                int ee = lane * 8 + e;
                float v = m1v[ee];
                if (v > cv) { cv = v; ci = m1i[ee]; }   // ascending scan => lowest idx on tie
            }
#pragma unroll
            for (int off = 16; off > 0; off >>= 1) {
                float ov = __shfl_xor_sync(0xffffffffu, cv, off);
                int   oi = __shfl_xor_sync(0xffffffffu, ci, off);
                if (ov > cv || (ov == cv && oi < ci)) { cv = ov; ci = oi; }
            }
            if (lane == 0) idx[(size_t)i * KNN + k] = ci;
            int e = ci >> 2;
            if (lane == (e >> 3)) {
                d[ci] = -CUDART_INF_F;
                int b4 = e * 4;
                float nv = d[b4]; int ni = b4;
                if (d[b4 + 1] > nv) { nv = d[b4 + 1]; ni = b4 + 1; }
                if (d[b4 + 2] > nv) { nv = d[b4 + 2]; ni = b4 + 2; }
                if (d[b4 + 3] > nv) { nv = d[b4 + 3]; ni = b4 + 3; }
                m1v[e] = nv; m1i[e] = ni;
            }
            __syncwarp();
        }
    }
}

// ================= h^T = (1+eps)*x + neighbor-sum, pre-split fp16 =============
__global__ __launch_bounds__(256) void hT_kernel(const float* __restrict__ xT,
                                                 const float* __restrict__ eT,
                                                 const int* __restrict__ idx,
                                                 __half* __restrict__ hh,
                                                 __half* __restrict__ hl) {
    __shared__ int nb[KNN];
    const int n = blockIdx.x;
    const int t = threadIdx.x;
    if (t < KNN) nb[t] = idx[n * KNN + t];
    __syncthreads();

    const size_t base = (size_t)n * CD + t * 4;
    float4 xv = *(const float4*)&xT[base];
    float4 ev = *(const float4*)&eT[base];
    float4 s;
    s.x = fmaf(ev.x, xv.x, xv.x);
    s.y = fmaf(ev.y, xv.y, xv.y);
    s.z = fmaf(ev.z, xv.z, xv.z);
    s.w = fmaf(ev.w, xv.w, xv.w);
#pragma unroll
    for (int k = 0; k < KNN; k++) {
        float4 nv = *(const float4*)&xT[(size_t)nb[k] * CD + t * 4];
        s.x += nv.x; s.y += nv.y; s.z += nv.z; s.w += nv.w;
    }
    __half hx, lx, hy, ly, hz, lz, hw, lw;
    split_h(s.x, hx, lx); split_h(s.y, hy, ly);
    split_h(s.z, hz, lz); split_h(s.w, hw, lw);
    ((uint2*)hh)[base / 4] = make_uint2(pack2(hx, hy), pack2(hz, hw));
    ((uint2*)hl)[base / 4] = make_uint2(pack2(lx, ly), pack2(lz, lw));
}

// ================= launch =================
extern "C" void kernel_launch(void* const* d_in, const int* in_sizes, int n_in,
                              void* d_out, int out_size) {
    const float* x   = (const float*)d_in[0];   // (C, N)
    const float* W   = (const float*)d_in[1];   // (O, C)
    const float* eps = (const float*)d_in[2];   // (C, N)
    float* out = (float*)d_out;                 // (O, N)

    float*  xT;   cudaGetSymbolAddress((void**)&xT,   g_xT);
    float*  eT;   cudaGetSymbolAddress((void**)&eT,   g_eT);
    __half* xh;   cudaGetSymbolAddress((void**)&xh,   g_xh);
    __half* xl;   cudaGetSymbolAddress((void**)&xl,   g_xl);
    __half* wh;   cudaGetSymbolAddress((void**)&wh,   g_wh);
    __half* wl;   cudaGetSymbolAddress((void**)&wl,   g_wl);
    __half* hh;   cudaGetSymbolAddress((void**)&hh,   g_hh);
    __half* hl;   cudaGetSymbolAddress((void**)&hl,   g_hl);
    float*  gram; cudaGetSymbolAddress((void**)&gram, g_gram);
    float*  x2;   cudaGetSymbolAddress((void**)&x2,   g_x2);
    int*    idx;  cudaGetSymbolAddress((void**)&idx,  g_idx);

    // stage bytes: 16384 + NT*128; 3 stages
    const int SMEM64  = 3 * (16384 + 64 * 128);    // 73728
    const int SMEM128 = 3 * (16384 + 128 * 128);   // 98304
    cudaFuncSetAttribute(mma_gemm<64>,  cudaFuncAttributeMaxDynamicSharedMemorySize, SMEM64);
    cudaFuncSetAttribute(mma_gemm<128>, cudaFuncAttributeMaxDynamicSharedMemorySize, SMEM128);

    transpose_kernel<<<dim3(ND / 32, CD / 32), dim3(32, 8)>>>(x, eps, xT, eT, xh, xl);
    wsplit_kernel<<<(OD * CD / 4) / 256, 256>>>(W, wh, wl);
    // Gram: M=1024, N=1024, CTA 128x64 -> 128 CTAs (diag fused)
    mma_gemm<64><<<dim3(ND / 64, ND / 128), 128, SMEM64>>>(xh, xl, xh, xl, gram, ND, x2);
    topk_kernel<<<ND, 256>>>(gram, x2, idx);
    hT_kernel<<<ND, 256>>>(xT, eT, idx, hh, hl);
    // Out: M=2048, N=1024, CTA 128x128 -> 128 CTAs
    mma_gemm<128><<<dim3(ND / 128, OD / 128), 128, SMEM128>>>(wh, wl, hh, hl, out, ND, nullptr);
}

// round 9
// speedup vs baseline: 2.2307x; 1.0302x over previous
#include <cuda_runtime.h>
#include <cuda_fp16.h>
#include <math_constants.h>
#include <cstdint>

#define CD 1024
#define ND 1024
#define OD 2048
#define KNN 20

// ---------------- scratch ----------------
__device__ __align__(16) float  g_xT[ND * CD];
__device__ __align__(16) float  g_eT[ND * CD];
__device__ __align__(16) __half g_xh[ND * CD];
__device__ __align__(16) __half g_xl[ND * CD];
__device__ __align__(16) __half g_wh[OD * CD];
__device__ __align__(16) __half g_wl[OD * CD];
__device__ __align__(16) __half g_hh[ND * CD];
__device__ __align__(16) __half g_hl[ND * CD];
__device__ __align__(16) float  g_gram[ND * ND];
__device__ __align__(16) float  g_x2[ND];
__device__            int    g_idx[ND * KNN];

// ---------------- helpers ----------------
__device__ __forceinline__ void split_h(float x, __half& h, __half& l) {
    h = __float2half_rn(x);
    l = __float2half_rn(x - __half2float(h));
}
__device__ __forceinline__ uint32_t pack2(__half a, __half b) {
    __half2 t = __halves2half2(a, b);
    return *(uint32_t*)&t;
}
__device__ __forceinline__ uint32_t s2u(const void* p) {
    uint32_t a;
    asm("{ .reg .u64 t; cvta.to.shared.u64 t, %1; cvt.u32.u64 %0, t; }" : "=r"(a) : "l"(p));
    return a;
}
__device__ __forceinline__ void cp16(uint32_t s, const void* g) {
    asm volatile("cp.async.cg.shared.global [%0], [%1], 16;" :: "r"(s), "l"(g));
}
#define CP_COMMIT() asm volatile("cp.async.commit_group;" ::: "memory")
#define CP_WAIT(n)  asm volatile("cp.async.wait_group %0;" :: "n"(n) : "memory")

__device__ __forceinline__ void ldm_x4(uint32_t* r, uint32_t addr) {
    asm volatile("ldmatrix.sync.aligned.m8n8.x4.shared.b16 {%0,%1,%2,%3}, [%4];"
                 : "=r"(r[0]), "=r"(r[1]), "=r"(r[2]), "=r"(r[3]) : "r"(addr));
}
__device__ __forceinline__ void mma_f16(float4& c, const uint32_t* a, const uint32_t* b) {
    asm volatile(
        "mma.sync.aligned.m16n8k16.row.col.f32.f16.f16.f32 "
        "{%0,%1,%2,%3}, {%4,%5,%6,%7}, {%8,%9}, {%0,%1,%2,%3};"
        : "+f"(c.x), "+f"(c.y), "+f"(c.z), "+f"(c.w)
        : "r"(a[0]), "r"(a[1]), "r"(a[2]), "r"(a[3]), "r"(b[0]), "r"(b[1]));
}
// swizzled byte offset for row r (64B rows), 16B chunk c
__device__ __forceinline__ uint32_t swoff(int r, int c) {
    return (uint32_t)(r * 64 + ((c ^ ((r >> 1) & 3)) << 4));
}

// ================= split-fp16 GEMM: cp.async x3 + ldmatrix, frag-reuse ========
// D[M,N] = (Ah+Al)[M,K] * (Bh+Bl)[N,K]^T, passes hh, lh, hl share fragments.
// CTA 128 x NT, 128 thr (2x2 warps), warp 64 x NT/2. K-chunk 32 halves.
// One __syncthreads per chunk (3-stage ring makes the tail barrier redundant).
template <int NT>
__global__ __launch_bounds__(128)
void mma_gemm(const __half* __restrict__ Ah_, const __half* __restrict__ Al_,
              const __half* __restrict__ Bh_, const __half* __restrict__ Bl_,
              float* __restrict__ D, int ldd, float* __restrict__ X2) {
    constexpr int NTN   = NT / 16;
    constexpr int ABY   = 128 * 64;            // bytes per A split
    constexpr int BOFF  = 2 * ABY;
    constexpr int BBY   = NT * 64;
    constexpr int STAGE = BOFF + 2 * BBY;
    constexpr int NI    = CD / 32;

    extern __shared__ char smem[];
    const uint32_t smb = s2u(smem);

    const int t = threadIdx.x, wid = t >> 5, lane = t & 31;
    const int wm = (wid >> 1) * 64, wn = (wid & 1) * (NT / 2);
    const int lq = lane & 3, lg = lane >> 2;
    const int m0 = blockIdx.y * 128, n0 = blockIdx.x * NT;

    const int rA = t >> 2, cA = t & 3;

    auto load_stage = [&](int chunk, int st) {
        const uint32_t sb = smb + st * STAGE;
        const size_t kofs = (size_t)chunk * 32;
#pragma unroll
        for (int j = 0; j < 4; j++) {
            int r = rA + j * 32;
            uint32_t dst = sb + swoff(r, cA);
            const size_t go = (size_t)(m0 + r) * CD + kofs + cA * 8;
            cp16(dst,       Ah_ + go);
            cp16(dst + ABY, Al_ + go);
        }
#pragma unroll
        for (int j = 0; j < NT / 32; j++) {
            int r = rA + j * 32;
            uint32_t dst = sb + BOFF + swoff(r, cA);
            const size_t go = (size_t)(n0 + r) * CD + kofs + cA * 8;
            cp16(dst,       Bh_ + go);
            cp16(dst + BBY, Bl_ + go);
        }
    };

    float4 c[4][NTN];
#pragma unroll
    for (int mt = 0; mt < 4; mt++)
#pragma unroll
        for (int nt = 0; nt < NTN; nt++) c[mt][nt] = make_float4(0.f, 0.f, 0.f, 0.f);

    load_stage(0, 0); CP_COMMIT();
    load_stage(1, 1); CP_COMMIT();

    // precomputed ldmatrix address components
    const int arow = lane & 15;                 // A: row within 16
    const int acsel = lane >> 4;                // A: chunk half
    const int brow = (lane & 7) + ((lane >> 4) << 3);   // B: row within 16 (paired tiles)
    const int bcsel = (lane >> 3) & 1;          // B: chunk half

    for (int i = 0; i < NI; i++) {
        CP_WAIT(1);
        __syncthreads();
        if (i + 2 < NI) load_stage(i + 2, (i + 2) % 3);
        CP_COMMIT();

        const uint32_t sb = smb + (i % 3) * STAGE;
#pragma unroll
        for (int kb = 0; kb < 2; kb++) {
            uint32_t ah[4][4], bh[2 * NTN];
#pragma unroll
            for (int mt = 0; mt < 4; mt++)
                ldm_x4(ah[mt], sb + swoff(wm + mt * 16 + arow, 2 * kb + acsel));
#pragma unroll
            for (int np = 0; np < NTN / 2; np++)
                ldm_x4(&bh[np * 4],
                       sb + BOFF + swoff(wn + np * 16 + brow, 2 * kb + bcsel));
            // pass hh
#pragma unroll
            for (int mt = 0; mt < 4; mt++)
#pragma unroll
                for (int nt = 0; nt < NTN; nt++)
                    mma_f16(c[mt][nt], ah[mt], &bh[nt * 2]);
            // pass lh (Al * Bh)
            {
                uint32_t al[4][4];
#pragma unroll
                for (int mt = 0; mt < 4; mt++)
                    ldm_x4(al[mt], sb + ABY + swoff(wm + mt * 16 + arow, 2 * kb + acsel));
#pragma unroll
                for (int mt = 0; mt < 4; mt++)
#pragma unroll
                    for (int nt = 0; nt < NTN; nt++)
                        mma_f16(c[mt][nt], al[mt], &bh[nt * 2]);
            }
            // pass hl (Ah * Bl)
            {
                uint32_t bl[2 * NTN];
#pragma unroll
                for (int np = 0; np < NTN / 2; np++)
                    ldm_x4(&bl[np * 4],
                           sb + BOFF + BBY + swoff(wn + np * 16 + brow, 2 * kb + bcsel));
#pragma unroll
                for (int mt = 0; mt < 4; mt++)
#pragma unroll
                    for (int nt = 0; nt < NTN; nt++)
                        mma_f16(c[mt][nt], ah[mt], &bl[nt * 2]);
            }
        }
    }

    // ---- epilogue (+ fused diag extraction for the Gram call) ----
#pragma unroll
    for (int mt = 0; mt < 4; mt++) {
        int r0 = m0 + wm + mt * 16 + lg;
#pragma unroll
        for (int nt = 0; nt < NTN; nt++) {
            int cb = n0 + wn + nt * 8 + lq * 2;
            *(float2*)&D[(size_t)r0 * ldd + cb]       = make_float2(c[mt][nt].x, c[mt][nt].y);
            *(float2*)&D[(size_t)(r0 + 8) * ldd + cb] = make_float2(c[mt][nt].z, c[mt][nt].w);
            if (X2) {
                if (r0 == cb)          X2[r0] = c[mt][nt].x;
                else if (r0 == cb + 1) X2[r0] = c[mt][nt].y;
                if (r0 + 8 == cb)          X2[r0 + 8] = c[mt][nt].z;
                else if (r0 + 8 == cb + 1) X2[r0 + 8] = c[mt][nt].w;
            }
        }
    }
}

// ================= transpose x, eps; emit fp32 + fp16-split x =================
__global__ __launch_bounds__(256) void transpose_kernel(
    const float* __restrict__ x, const float* __restrict__ e,
    float* __restrict__ xT, float* __restrict__ eT,
    __half* __restrict__ xh, __half* __restrict__ xl) {
    __shared__ float tx[32][33], te[32][33];
    const int i0 = blockIdx.x * 32;   // N
    const int j0 = blockIdx.y * 32;   // C
    const int c = threadIdx.x, r = threadIdx.y;
#pragma unroll
    for (int k = 0; k < 32; k += 8) {
        tx[r + k][c] = x[(size_t)(j0 + r + k) * ND + i0 + c];
        te[r + k][c] = e[(size_t)(j0 + r + k) * ND + i0 + c];
    }
    __syncthreads();
#pragma unroll
    for (int k = 0; k < 32; k += 8) {
        size_t o = (size_t)(i0 + r + k) * CD + j0 + c;
        float v = tx[c][r + k];
        xT[o] = v;
        eT[o] = te[c][r + k];
        __half h, l;
        split_h(v, h, l);
        xh[o] = h;
        xl[o] = l;
    }
}

// ================= W split =================
__global__ __launch_bounds__(256) void wsplit_kernel(const float* __restrict__ W,
                                                     __half* __restrict__ Wh,
                                                     __half* __restrict__ Wl) {
    int i = blockIdx.x * blockDim.x + threadIdx.x;   // over OD*CD/4
    float4 v = ((const float4*)W)[i];
    __half hx, lx, hy, ly, hz, lz, hw, lw;
    split_h(v.x, hx, lx); split_h(v.y, hy, ly);
    split_h(v.z, hz, lz); split_h(v.w, hw, lw);
    ((uint2*)Wh)[i] = make_uint2(pack2(hx, hy), pack2(hz, hw));
    ((uint2*)Wl)[i] = make_uint2(pack2(lx, ly), pack2(lz, lw));
}

// ================= top-20: warp-per-row, no block barriers =================
// Each lane owns 32 elements (8 float4 slices); running local max in registers.
// Extraction: butterfly argmax (tie -> lowest index), owner lane rescans its 32.
__global__ __launch_bounds__(256) void topk_kernel(const float* __restrict__ G,
                                                   const float* __restrict__ x2,
                                                   int* __restrict__ idx) {
    __shared__ float d[8][ND];
    const int t = threadIdx.x, wid = t >> 5, lane = t & 31;
    const int row = blockIdx.x * 8 + wid;
    const float x2i = x2[row];
    float* dr = d[wid];

    float bv = -CUDART_INF_F; int bi = 1 << 30;
#pragma unroll
    for (int j = 0; j < 8; j++) {
        const int gi = j * 128 + lane * 4;
        float4 g = *(const float4*)&G[(size_t)row * ND + gi];
        float4 q = *(const float4*)&x2[gi];
        float v0 = 2.f * g.x - x2i - q.x;
        float v1 = 2.f * g.y - x2i - q.y;
        float v2 = 2.f * g.z - x2i - q.z;
        float v3 = 2.f * g.w - x2i - q.w;
        *(float4*)&dr[gi] = make_float4(v0, v1, v2, v3);
        if (v0 > bv) { bv = v0; bi = gi; }
        if (v1 > bv) { bv = v1; bi = gi + 1; }
        if (v2 > bv) { bv = v2; bi = gi + 2; }
        if (v3 > bv) { bv = v3; bi = gi + 3; }
    }
    __syncwarp();

    for (int k = 0; k < KNN; k++) {
        float cv = bv; int ci = bi;
#pragma unroll
        for (int off = 16; off > 0; off >>= 1) {
            float ov = __shfl_xor_sync(0xffffffffu, cv, off);
            int   oi = __shfl_xor_sync(0xffffffffu, ci, off);
            if (ov > cv || (ov == cv && oi < ci)) { cv = ov; ci = oi; }
        }
        if (lane == 0) idx[(size_t)row * KNN + k] = ci;
        if (lane == ((ci >> 2) & 31)) {
            dr[ci] = -CUDART_INF_F;
            bv = -CUDART_INF_F; bi = 1 << 30;
#pragma unroll
            for (int j = 0; j < 8; j++) {
                const int gi = j * 128 + lane * 4;
                float4 v = *(const float4*)&dr[gi];
                if (v.x > bv) { bv = v.x; bi = gi; }
                if (v.y > bv) { bv = v.y; bi = gi + 1; }
                if (v.z > bv) { bv = v.z; bi = gi + 2; }
                if (v.w > bv) { bv = v.w; bi = gi + 3; }
            }
        }
        __syncwarp();
    }
}

// ================= h^T = (1+eps)*x + neighbor-sum, pre-split fp16 =============
__global__ __launch_bounds__(256) void hT_kernel(const float* __restrict__ xT,
                                                 const float* __restrict__ eT,
                                                 const int* __restrict__ idx,
                                                 __half* __restrict__ hh,
                                                 __half* __restrict__ hl) {
    __shared__ int nb[KNN];
    const int n = blockIdx.x;
    const int t = threadIdx.x;
    if (t < KNN) nb[t] = idx[n * KNN + t];
    __syncthreads();

    const size_t base = (size_t)n * CD + t * 4;
    float4 xv = *(const float4*)&xT[base];
    float4 ev = *(const float4*)&eT[base];
    float4 s;
    s.x = fmaf(ev.x, xv.x, xv.x);
    s.y = fmaf(ev.y, xv.y, xv.y);
    s.z = fmaf(ev.z, xv.z, xv.z);
    s.w = fmaf(ev.w, xv.w, xv.w);
#pragma unroll
    for (int k = 0; k < KNN; k++) {
        float4 nv = *(const float4*)&xT[(size_t)nb[k] * CD + t * 4];
        s.x += nv.x; s.y += nv.y; s.z += nv.z; s.w += nv.w;
    }
    __half hx, lx, hy, ly, hz, lz, hw, lw;
    split_h(s.x, hx, lx); split_h(s.y, hy, ly);
    split_h(s.z, hz, lz); split_h(s.w, hw, lw);
    ((uint2*)hh)[base / 4] = make_uint2(pack2(hx, hy), pack2(hz, hw));
    ((uint2*)hl)[base / 4] = make_uint2(pack2(lx, ly), pack2(lz, lw));
}

// ================= launch =================
extern "C" void kernel_launch(void* const* d_in, const int* in_sizes, int n_in,
                              void* d_out, int out_size) {
    const float* x   = (const float*)d_in[0];   // (C, N)
    const float* W   = (const float*)d_in[1];   // (O, C)
    const float* eps = (const float*)d_in[2];   // (C, N)
    float* out = (float*)d_out;                 // (O, N)

    float*  xT;   cudaGetSymbolAddress((void**)&xT,   g_xT);
    float*  eT;   cudaGetSymbolAddress((void**)&eT,   g_eT);
    __half* xh;   cudaGetSymbolAddress((void**)&xh,   g_xh);
    __half* xl;   cudaGetSymbolAddress((void**)&xl,   g_xl);
    __half* wh;   cudaGetSymbolAddress((void**)&wh,   g_wh);
    __half* wl;   cudaGetSymbolAddress((void**)&wl,   g_wl);
    __half* hh;   cudaGetSymbolAddress((void**)&hh,   g_hh);
    __half* hl;   cudaGetSymbolAddress((void**)&hl,   g_hl);
    float*  gram; cudaGetSymbolAddress((void**)&gram, g_gram);
    float*  x2;   cudaGetSymbolAddress((void**)&x2,   g_x2);
    int*    idx;  cudaGetSymbolAddress((void**)&idx,  g_idx);

    const int SMEM64  = 3 * (16384 + 64 * 128);    // 73728
    const int SMEM128 = 3 * (16384 + 128 * 128);   // 98304
    cudaFuncSetAttribute(mma_gemm<64>,  cudaFuncAttributeMaxDynamicSharedMemorySize, SMEM64);
    cudaFuncSetAttribute(mma_gemm<128>, cudaFuncAttributeMaxDynamicSharedMemorySize, SMEM128);

    transpose_kernel<<<dim3(ND / 32, CD / 32), dim3(32, 8)>>>(x, eps, xT, eT, xh, xl);
    wsplit_kernel<<<(OD * CD / 4) / 256, 256>>>(W, wh, wl);
    // Gram: M=1024, N=1024, CTA 128x64 -> 128 CTAs (diag fused)
    mma_gemm<64><<<dim3(ND / 64, ND / 128), 128, SMEM64>>>(xh, xl, xh, xl, gram, ND, x2);
    topk_kernel<<<ND / 8, 256>>>(gram, x2, idx);
    hT_kernel<<<ND, 256>>>(xT, eT, idx, hh, hl);
    // Out: M=2048, N=1024, CTA 128x128 -> 128 CTAs
    mma_gemm<128><<<dim3(ND / 128, OD / 128), 128, SMEM128>>>(wh, wl, hh, hl, out, ND, nullptr);
}

// round 10
// speedup vs baseline: 2.4954x; 1.1187x over previous
#include <cuda_runtime.h>
#include <cuda_fp16.h>
#include <math_constants.h>
#include <cstdint>

#define CD 1024
#define ND 1024
#define OD 2048
#define KNN 20

// ---------------- scratch ----------------
__device__ __align__(16) float  g_xT[ND * CD];
__device__ __align__(16) float  g_eT[ND * CD];
__device__ __align__(16) __half g_xh[ND * CD];
__device__ __align__(16) __half g_xl[ND * CD];
__device__ __align__(16) __half g_wh[OD * CD];
__device__ __align__(16) __half g_wl[OD * CD];
__device__ __align__(16) __half g_hh[ND * CD];
__device__ __align__(16) float  g_gram[ND * ND];
__device__ __align__(16) float  g_x2[ND];
__device__            int    g_idx[ND * KNN];

// ---------------- helpers ----------------
__device__ __forceinline__ void split_h(float x, __half& h, __half& l) {
    h = __float2half_rn(x);
    l = __float2half_rn(x - __half2float(h));
}
__device__ __forceinline__ uint32_t pack2(__half a, __half b) {
    __half2 t = __halves2half2(a, b);
    return *(uint32_t*)&t;
}
__device__ __forceinline__ uint32_t s2u(const void* p) {
    uint32_t a;
    asm("{ .reg .u64 t; cvta.to.shared.u64 t, %1; cvt.u32.u64 %0, t; }" : "=r"(a) : "l"(p));
    return a;
}
__device__ __forceinline__ void cp16(uint32_t s, const void* g) {
    asm volatile("cp.async.cg.shared.global [%0], [%1], 16;" :: "r"(s), "l"(g));
}
#define CP_COMMIT() asm volatile("cp.async.commit_group;" ::: "memory")
#define CP_WAIT(n)  asm volatile("cp.async.wait_group %0;" :: "n"(n) : "memory")

__device__ __forceinline__ void ldm_x4(uint32_t* r, uint32_t addr) {
    asm volatile("ldmatrix.sync.aligned.m8n8.x4.shared.b16 {%0,%1,%2,%3}, [%4];"
                 : "=r"(r[0]), "=r"(r[1]), "=r"(r[2]), "=r"(r[3]) : "r"(addr));
}
__device__ __forceinline__ void mma_f16(float4& c, const uint32_t* a, const uint32_t* b) {
    asm volatile(
        "mma.sync.aligned.m16n8k16.row.col.f32.f16.f16.f32 "
        "{%0,%1,%2,%3}, {%4,%5,%6,%7}, {%8,%9}, {%0,%1,%2,%3};"
        : "+f"(c.x), "+f"(c.y), "+f"(c.z), "+f"(c.w)
        : "r"(a[0]), "r"(a[1]), "r"(a[2]), "r"(a[3]), "r"(b[0]), "r"(b[1]));
}
// swizzled byte offset for row r (64B rows), 16B chunk c
__device__ __forceinline__ uint32_t swoff(int r, int c) {
    return (uint32_t)(r * 64 + ((c ^ ((r >> 1) & 3)) << 4));
}

// ============ split-fp16 GEMM: 256 thr, cp.async x3, ldmatrix, frag-reuse ======
// D[M,N] = (Ah+Al)[M,K] * (Bh+Bl)[N,K]^T. PASSES=3: hh+lh+hl; PASSES=2: hh+lh
// (Bl never loaded). CTA 128 x NT, 8 warps in (8/WNC) x WNC grid.
template <int NT, int WNC, int PASSES>
__global__ __launch_bounds__(256)
void mma_gemm(const __half* __restrict__ Ah_, const __half* __restrict__ Al_,
              const __half* __restrict__ Bh_, const __half* __restrict__ Bl_,
              float* __restrict__ D, int ldd, float* __restrict__ X2) {
    constexpr int WMC   = 8 / WNC;
    constexpr int MT    = 128 / (WMC * 16);       // m16 tiles per warp
    constexpr int NTN   = NT / (WNC * 8);         // n8 tiles per warp (must be even)
    constexpr int ABY   = 128 * 64;
    constexpr int BOFF  = 2 * ABY;
    constexpr int BBY   = NT * 64;
    constexpr int STAGE = BOFF + (PASSES == 3 ? 2 : 1) * BBY;
    constexpr int NI    = CD / 32;

    extern __shared__ char smem[];
    const uint32_t smb = s2u(smem);

    const int t = threadIdx.x, wid = t >> 5, lane = t & 31;
    const int wm = (wid / WNC) * (128 / WMC);
    const int wn = (wid % WNC) * (NT / WNC);
    const int lq = lane & 3, lg = lane >> 2;
    const int m0 = blockIdx.y * 128, n0 = blockIdx.x * NT;

    const int rA = t >> 2, cA = t & 3;            // rA 0..63

    auto load_stage = [&](int chunk, int st) {
        const uint32_t sb = smb + st * STAGE;
        const size_t kofs = (size_t)chunk * 32;
#pragma unroll
        for (int j = 0; j < 2; j++) {
            int r = rA + j * 64;
            uint32_t dst = sb + swoff(r, cA);
            const size_t go = (size_t)(m0 + r) * CD + kofs + cA * 8;
            cp16(dst,       Ah_ + go);
            cp16(dst + ABY, Al_ + go);
        }
#pragma unroll
        for (int j = 0; j < NT / 64; j++) {
            int r = rA + j * 64;
            uint32_t dst = sb + BOFF + swoff(r, cA);
            const size_t go = (size_t)(n0 + r) * CD + kofs + cA * 8;
            cp16(dst, Bh_ + go);
            if (PASSES == 3) cp16(dst + BBY, Bl_ + go);
        }
    };

    float4 c[MT][NTN];
#pragma unroll
    for (int mt = 0; mt < MT; mt++)
#pragma unroll
        for (int nt = 0; nt < NTN; nt++) c[mt][nt] = make_float4(0.f, 0.f, 0.f, 0.f);

    load_stage(0, 0); CP_COMMIT();
    load_stage(1, 1); CP_COMMIT();

    const int arow = lane & 15;
    const int acsel = lane >> 4;
    const int brow = (lane & 7) + ((lane >> 4) << 3);
    const int bcsel = (lane >> 3) & 1;

    for (int i = 0; i < NI; i++) {
        CP_WAIT(1);
        __syncthreads();
        if (i + 2 < NI) load_stage(i + 2, (i + 2) % 3);
        CP_COMMIT();

        const uint32_t sb = smb + (i % 3) * STAGE;
#pragma unroll
        for (int kb = 0; kb < 2; kb++) {
            uint32_t ah[MT][4], bh[2 * NTN];
#pragma unroll
            for (int mt = 0; mt < MT; mt++)
                ldm_x4(ah[mt], sb + swoff(wm + mt * 16 + arow, 2 * kb + acsel));
#pragma unroll
            for (int np = 0; np < NTN / 2; np++)
                ldm_x4(&bh[np * 4],
                       sb + BOFF + swoff(wn + np * 16 + brow, 2 * kb + bcsel));
            // pass hh
#pragma unroll
            for (int mt = 0; mt < MT; mt++)
#pragma unroll
                for (int nt = 0; nt < NTN; nt++)
                    mma_f16(c[mt][nt], ah[mt], &bh[nt * 2]);
            // pass lh (Al * Bh)
            {
                uint32_t al[MT][4];
#pragma unroll
                for (int mt = 0; mt < MT; mt++)
                    ldm_x4(al[mt], sb + ABY + swoff(wm + mt * 16 + arow, 2 * kb + acsel));
#pragma unroll
                for (int mt = 0; mt < MT; mt++)
#pragma unroll
                    for (int nt = 0; nt < NTN; nt++)
                        mma_f16(c[mt][nt], al[mt], &bh[nt * 2]);
            }
            // pass hl (Ah * Bl)
            if (PASSES == 3) {
                uint32_t bl[2 * NTN];
#pragma unroll
                for (int np = 0; np < NTN / 2; np++)
                    ldm_x4(&bl[np * 4],
                           sb + BOFF + BBY + swoff(wn + np * 16 + brow, 2 * kb + bcsel));
#pragma unroll
                for (int mt = 0; mt < MT; mt++)
#pragma unroll
                    for (int nt = 0; nt < NTN; nt++)
                        mma_f16(c[mt][nt], ah[mt], &bl[nt * 2]);
            }
        }
    }

    // ---- epilogue (+ fused diag extraction for the Gram call) ----
#pragma unroll
    for (int mt = 0; mt < MT; mt++) {
        int r0 = m0 + wm + mt * 16 + lg;
#pragma unroll
        for (int nt = 0; nt < NTN; nt++) {
            int cb = n0 + wn + nt * 8 + lq * 2;
            *(float2*)&D[(size_t)r0 * ldd + cb]       = make_float2(c[mt][nt].x, c[mt][nt].y);
            *(float2*)&D[(size_t)(r0 + 8) * ldd + cb] = make_float2(c[mt][nt].z, c[mt][nt].w);
            if (X2) {
                if (r0 == cb)          X2[r0] = c[mt][nt].x;
                else if (r0 == cb + 1) X2[r0] = c[mt][nt].y;
                if (r0 + 8 == cb)          X2[r0 + 8] = c[mt][nt].z;
                else if (r0 + 8 == cb + 1) X2[r0 + 8] = c[mt][nt].w;
            }
        }
    }
}

// ================= transpose x, eps; emit fp32 + fp16-split x =================
__global__ __launch_bounds__(256) void transpose_kernel(
    const float* __restrict__ x, const float* __restrict__ e,
    float* __restrict__ xT, float* __restrict__ eT,
    __half* __restrict__ xh, __half* __restrict__ xl) {
    __shared__ float tx[32][33], te[32][33];
    const int i0 = blockIdx.x * 32;   // N
    const int j0 = blockIdx.y * 32;   // C
    const int c = threadIdx.x, r = threadIdx.y;
#pragma unroll
    for (int k = 0; k < 32; k += 8) {
        tx[r + k][c] = x[(size_t)(j0 + r + k) * ND + i0 + c];
        te[r + k][c] = e[(size_t)(j0 + r + k) * ND + i0 + c];
    }
    __syncthreads();
#pragma unroll
    for (int k = 0; k < 32; k += 8) {
        size_t o = (size_t)(i0 + r + k) * CD + j0 + c;
        float v = tx[c][r + k];
        xT[o] = v;
        eT[o] = te[c][r + k];
        __half h, l;
        split_h(v, h, l);
        xh[o] = h;
        xl[o] = l;
    }
}

// ================= W split =================
__global__ __launch_bounds__(256) void wsplit_kernel(const float* __restrict__ W,
                                                     __half* __restrict__ Wh,
                                                     __half* __restrict__ Wl) {
    int i = blockIdx.x * blockDim.x + threadIdx.x;   // over OD*CD/4
    float4 v = ((const float4*)W)[i];
    __half hx, lx, hy, ly, hz, lz, hw, lw;
    split_h(v.x, hx, lx); split_h(v.y, hy, ly);
    split_h(v.z, hz, lz); split_h(v.w, hw, lw);
    ((uint2*)Wh)[i] = make_uint2(pack2(hx, hy), pack2(hz, hw));
    ((uint2*)Wl)[i] = make_uint2(pack2(lx, ly), pack2(lz, lw));
}

// ================= top-20: warp-per-row, fully register-resident ===============
// Lane owns 8 float4 slices (32 dists) + per-slice maxes, all in registers.
// Extraction: 8-cmp scan + butterfly argmax (tie -> lowest index) + owner's
// predicated register repair. No shared memory at all.
__global__ __launch_bounds__(128) void topk_kernel(const float* __restrict__ G,
                                                   const float* __restrict__ x2,
                                                   int* __restrict__ idx) {
    const int t = threadIdx.x, wid = t >> 5, lane = t & 31;
    const int row = blockIdx.x * 4 + wid;
    const float x2i = x2[row];

    float4 v[8];
    float  mv[8];
    int    mi[8];
#pragma unroll
    for (int j = 0; j < 8; j++) {
        const int gi = j * 128 + lane * 4;
        float4 g = *(const float4*)&G[(size_t)row * ND + gi];
        float4 q = *(const float4*)&x2[gi];
        v[j].x = 2.f * g.x - x2i - q.x;
        v[j].y = 2.f * g.y - x2i - q.y;
        v[j].z = 2.f * g.z - x2i - q.z;
        v[j].w = 2.f * g.w - x2i - q.w;
        float bv = v[j].x; int bi = gi;
        if (v[j].y > bv) { bv = v[j].y; bi = gi + 1; }
        if (v[j].z > bv) { bv = v[j].z; bi = gi + 2; }
        if (v[j].w > bv) { bv = v[j].w; bi = gi + 3; }
        mv[j] = bv; mi[j] = bi;
    }

    for (int k = 0; k < KNN; k++) {
        float cv = mv[0]; int ci = mi[0];
#pragma unroll
        for (int j = 1; j < 8; j++)
            if (mv[j] > cv) { cv = mv[j]; ci = mi[j]; }   // ascending j => lowest idx on tie
#pragma unroll
        for (int off = 16; off > 0; off >>= 1) {
            float ov = __shfl_xor_sync(0xffffffffu, cv, off);
            int   oi = __shfl_xor_sync(0xffffffffu, ci, off);
            if (ov > cv || (ov == cv && oi < ci)) { cv = ov; ci = oi; }
        }
        if (lane == 0) idx[(size_t)row * KNN + k] = ci;
        if (lane == ((ci >> 2) & 31)) {
            const int jj = ci >> 7, cc = ci & 3;
#pragma unroll
            for (int j = 0; j < 8; j++) {
                if (j == jj) {
                    if (cc == 0) v[j].x = -CUDART_INF_F;
                    else if (cc == 1) v[j].y = -CUDART_INF_F;
                    else if (cc == 2) v[j].z = -CUDART_INF_F;
                    else v[j].w = -CUDART_INF_F;
                    const int gi = j * 128 + lane * 4;
                    float bv = v[j].x; int bi = gi;
                    if (v[j].y > bv) { bv = v[j].y; bi = gi + 1; }
                    if (v[j].z > bv) { bv = v[j].z; bi = gi + 2; }
                    if (v[j].w > bv) { bv = v[j].w; bi = gi + 3; }
                    mv[j] = bv; mi[j] = bi;
                }
            }
        }
    }
}

// ====== h^T = (1+eps)*x + neighbor-sum, pre-split fp16 (hi only needed) =======
__global__ __launch_bounds__(256) void hT_kernel(const float* __restrict__ xT,
                                                 const float* __restrict__ eT,
                                                 const int* __restrict__ idx,
                                                 __half* __restrict__ hh) {
    __shared__ int nb[KNN];
    const int n = blockIdx.x;
    const int t = threadIdx.x;
    if (t < KNN) nb[t] = idx[n * KNN + t];
    __syncthreads();

    const size_t base = (size_t)n * CD + t * 4;
    float4 xv = *(const float4*)&xT[base];
    float4 ev = *(const float4*)&eT[base];
    float4 s;
    s.x = fmaf(ev.x, xv.x, xv.x);
    s.y = fmaf(ev.y, xv.y, xv.y);
    s.z = fmaf(ev.z, xv.z, xv.z);
    s.w = fmaf(ev.w, xv.w, xv.w);
#pragma unroll
    for (int k = 0; k < KNN; k++) {
        float4 nv = *(const float4*)&xT[(size_t)nb[k] * CD + t * 4];
        s.x += nv.x; s.y += nv.y; s.z += nv.z; s.w += nv.w;
    }
    ((uint2*)hh)[base / 4] = make_uint2(
        pack2(__float2half_rn(s.x), __float2half_rn(s.y)),
        pack2(__float2half_rn(s.z), __float2half_rn(s.w)));
}

// ================= launch =================
extern "C" void kernel_launch(void* const* d_in, const int* in_sizes, int n_in,
                              void* d_out, int out_size) {
    const float* x   = (const float*)d_in[0];   // (C, N)
    const float* W   = (const float*)d_in[1];   // (O, C)
    const float* eps = (const float*)d_in[2];   // (C, N)
    float* out = (float*)d_out;                 // (O, N)

    float*  xT;   cudaGetSymbolAddress((void**)&xT,   g_xT);
    float*  eT;   cudaGetSymbolAddress((void**)&eT,   g_eT);
    __half* xh;   cudaGetSymbolAddress((void**)&xh,   g_xh);
    __half* xl;   cudaGetSymbolAddress((void**)&xl,   g_xl);
    __half* wh;   cudaGetSymbolAddress((void**)&wh,   g_wh);
    __half* wl;   cudaGetSymbolAddress((void**)&wl,   g_wl);
    __half* hh;   cudaGetSymbolAddress((void**)&hh,   g_hh);
    float*  gram; cudaGetSymbolAddress((void**)&gram, g_gram);
    float*  x2;   cudaGetSymbolAddress((void**)&x2,   g_x2);
    int*    idx;  cudaGetSymbolAddress((void**)&idx,  g_idx);

    // Gram: NT=64, 3 passes -> stage 16384+8192; Out: NT=128, 2 passes -> same
    const int SMEM = 3 * (16384 + 8192);   // 73728 both
    cudaFuncSetAttribute(mma_gemm<64, 2, 3>,
                         cudaFuncAttributeMaxDynamicSharedMemorySize, SMEM);
    cudaFuncSetAttribute(mma_gemm<128, 4, 2>,
                         cudaFuncAttributeMaxDynamicSharedMemorySize, SMEM);

    transpose_kernel<<<dim3(ND / 32, CD / 32), dim3(32, 8)>>>(x, eps, xT, eT, xh, xl);
    wsplit_kernel<<<(OD * CD / 4) / 256, 256>>>(W, wh, wl);
    // Gram: M=1024, N=1024, CTA 128x64 -> 128 CTAs, 3-pass (exact topk), diag fused
    mma_gemm<64, 2, 3><<<dim3(ND / 64, ND / 128), 256, SMEM>>>(xh, xl, xh, xl, gram, ND, x2);
    topk_kernel<<<ND / 4, 128>>>(gram, x2, idx);
    hT_kernel<<<ND, 256>>>(xT, eT, idx, hh);
    // Out: M=2048, N=1024, CTA 128x128 -> 128 CTAs, 2-pass (hh + lh)
    mma_gemm<128, 4, 2><<<dim3(ND / 128, OD / 128), 256, SMEM>>>(wh, wl, hh, nullptr, out, ND, nullptr);
}

// round 12
// speedup vs baseline: 3.4634x; 1.3879x over previous
#include <cuda_runtime.h>
#include <cuda_fp16.h>
#include <math_constants.h>
#include <cstdint>

#define CD 1024
#define ND 1024
#define OD 2048
#define KNN 20

// ---------------- scratch ----------------
__device__ __align__(16) float  g_xT[ND * CD];
__device__ __align__(16) float  g_eT[ND * CD];
__device__ __align__(16) __half g_xh[ND * CD];
__device__ __align__(16) __half g_xl[ND * CD];
__device__ __align__(16) __half g_wh[OD * CD];
__device__ __align__(16) __half g_hh[ND * CD];
__device__ __align__(16) float  g_gram[ND * ND];
__device__ __align__(16) float  g_x2[ND];
__device__            int    g_idx[ND * KNN];

// ---------------- helpers ----------------
__device__ __forceinline__ void split_h(float x, __half& h, __half& l) {
    h = __float2half_rn(x);
    l = __float2half_rn(x - __half2float(h));
}
__device__ __forceinline__ uint32_t pack2(__half a, __half b) {
    __half2 t = __halves2half2(a, b);
    return *(uint32_t*)&t;
}
__device__ __forceinline__ uint32_t s2u(const void* p) {
    uint32_t a;
    asm("{ .reg .u64 t; cvta.to.shared.u64 t, %1; cvt.u32.u64 %0, t; }" : "=r"(a) : "l"(p));
    return a;
}
__device__ __forceinline__ void cp16(uint32_t s, const void* g) {
    asm volatile("cp.async.cg.shared.global [%0], [%1], 16;" :: "r"(s), "l"(g));
}
#define CP_COMMIT() asm volatile("cp.async.commit_group;" ::: "memory")
#define CP_WAIT(n)  asm volatile("cp.async.wait_group %0;" :: "n"(n) : "memory")

__device__ __forceinline__ void ldm_x4(uint32_t* r, uint32_t addr) {
    asm volatile("ldmatrix.sync.aligned.m8n8.x4.shared.b16 {%0,%1,%2,%3}, [%4];"
                 : "=r"(r[0]), "=r"(r[1]), "=r"(r[2]), "=r"(r[3]) : "r"(addr));
}
__device__ __forceinline__ void mma_f16(float4& c, const uint32_t* a, const uint32_t* b) {
    asm volatile(
        "mma.sync.aligned.m16n8k16.row.col.f32.f16.f16.f32 "
        "{%0,%1,%2,%3}, {%4,%5,%6,%7}, {%8,%9}, {%0,%1,%2,%3};"
        : "+f"(c.x), "+f"(c.y), "+f"(c.z), "+f"(c.w)
        : "r"(a[0]), "r"(a[1]), "r"(a[2]), "r"(a[3]), "r"(b[0]), "r"(b[1]));
}
// swizzled byte offset for row r (64B rows), 16B chunk c
__device__ __forceinline__ uint32_t swoff(int r, int c) {
    return (uint32_t)(r * 64 + ((c ^ ((r >> 1) & 3)) << 4));
}

// ============ split-fp16 GEMM: 256 thr, cp.async x3, ldmatrix ================
// D[M,N] = A[M,K]*B[N,K]^T. PASSES: 3 = AhBh+AlBh+AhBl, 2 = AhBh+AlBh,
// 1 = AhBh (plain fp16). SYMM: triangular 64-tile grid; off-diag CTAs also
// write the transposed tile (G symmetric).
template <int MTILE, int NT, int WNC, int PASSES, bool SYMM>
__global__ __launch_bounds__(256)
void mma_gemm(const __half* __restrict__ Ah_, const __half* __restrict__ Al_,
              const __half* __restrict__ Bh_, const __half* __restrict__ Bl_,
              float* __restrict__ D, int ldd, float* __restrict__ X2) {
    constexpr int WMC   = 8 / WNC;
    constexpr int MT    = MTILE / (WMC * 16);
    constexpr int NTN   = NT / (WNC * 8);          // even (paired x4 B loads)
    constexpr int ABY   = MTILE * 64;
    constexpr int NA    = (PASSES >= 2) ? 2 : 1;
    constexpr int NB    = (PASSES == 3) ? 2 : 1;
    constexpr int BOFF  = NA * ABY;
    constexpr int BBY   = NT * 64;
    constexpr int STAGE = BOFF + NB * BBY;
    constexpr int NI    = CD / 32;

    extern __shared__ char smem[];
    const uint32_t smb = s2u(smem);

    const int t = threadIdx.x, wid = t >> 5, lane = t & 31;
    const int wm = (wid / WNC) * (MTILE / WMC);
    const int wn = (wid % WNC) * (NT / WNC);
    const int lq = lane & 3, lg = lane >> 2;

    int m0, n0;
    if (SYMM) {
        int b = blockIdx.x, ti = 0;
        while (b >= 16 - ti) { b -= 16 - ti; ti++; }
        m0 = ti * 64; n0 = (ti + b) * 64;
    } else {
        m0 = blockIdx.y * MTILE; n0 = blockIdx.x * NT;
    }

    const int rA = t >> 2, cA = t & 3;

    auto load_stage = [&](int chunk, int st) {
        const uint32_t sb = smb + st * STAGE;
        const size_t kofs = (size_t)chunk * 32;
#pragma unroll
        for (int j = 0; j < MTILE / 64; j++) {
            int r = rA + j * 64;
            uint32_t dst = sb + swoff(r, cA);
            const size_t go = (size_t)(m0 + r) * CD + kofs + cA * 8;
            cp16(dst, Ah_ + go);
            if (PASSES >= 2) cp16(dst + ABY, Al_ + go);
        }
#pragma unroll
        for (int j = 0; j < NT / 64; j++) {
            int r = rA + j * 64;
            uint32_t dst = sb + BOFF + swoff(r, cA);
            const size_t go = (size_t)(n0 + r) * CD + kofs + cA * 8;
            cp16(dst, Bh_ + go);
            if (PASSES == 3) cp16(dst + BBY, Bl_ + go);
        }
    };

    float4 c[MT][NTN];
#pragma unroll
    for (int mt = 0; mt < MT; mt++)
#pragma unroll
        for (int nt = 0; nt < NTN; nt++) c[mt][nt] = make_float4(0.f, 0.f, 0.f, 0.f);

    load_stage(0, 0); CP_COMMIT();
    load_stage(1, 1); CP_COMMIT();

    const int arow = lane & 15;
    const int acsel = lane >> 4;
    const int brow = (lane & 7) + ((lane >> 4) << 3);
    const int bcsel = (lane >> 3) & 1;

    for (int i = 0; i < NI; i++) {
        CP_WAIT(1);
        __syncthreads();
        if (i + 2 < NI) load_stage(i + 2, (i + 2) % 3);
        CP_COMMIT();

        const uint32_t sb = smb + (i % 3) * STAGE;
#pragma unroll
        for (int kb = 0; kb < 2; kb++) {
            uint32_t ah[MT][4], bh[2 * NTN];
#pragma unroll
            for (int mt = 0; mt < MT; mt++)
                ldm_x4(ah[mt], sb + swoff(wm + mt * 16 + arow, 2 * kb + acsel));
#pragma unroll
            for (int np = 0; np < NTN / 2; np++)
                ldm_x4(&bh[np * 4],
                       sb + BOFF + swoff(wn + np * 16 + brow, 2 * kb + bcsel));
#pragma unroll
            for (int mt = 0; mt < MT; mt++)
#pragma unroll
                for (int nt = 0; nt < NTN; nt++)
                    mma_f16(c[mt][nt], ah[mt], &bh[nt * 2]);
            if (PASSES >= 2) {
                uint32_t al[MT][4];
#pragma unroll
                for (int mt = 0; mt < MT; mt++)
                    ldm_x4(al[mt], sb + ABY + swoff(wm + mt * 16 + arow, 2 * kb + acsel));
#pragma unroll
                for (int mt = 0; mt < MT; mt++)
#pragma unroll
                    for (int nt = 0; nt < NTN; nt++)
                        mma_f16(c[mt][nt], al[mt], &bh[nt * 2]);
            }
            if (PASSES == 3) {
                uint32_t bl[2 * NTN];
#pragma unroll
                for (int np = 0; np < NTN / 2; np++)
                    ldm_x4(&bl[np * 4],
                           sb + BOFF + BBY + swoff(wn + np * 16 + brow, 2 * kb + bcsel));
#pragma unroll
                for (int mt = 0; mt < MT; mt++)
#pragma unroll
                    for (int nt = 0; nt < NTN; nt++)
                        mma_f16(c[mt][nt], ah[mt], &bl[nt * 2]);
            }
        }
    }

    // ---- epilogue: direct writes (+ diag extraction) ----
#pragma unroll
    for (int mt = 0; mt < MT; mt++) {
        int r0 = m0 + wm + mt * 16 + lg;
#pragma unroll
        for (int nt = 0; nt < NTN; nt++) {
            int cb = n0 + wn + nt * 8 + lq * 2;
            *(float2*)&D[(size_t)r0 * ldd + cb]       = make_float2(c[mt][nt].x, c[mt][nt].y);
            *(float2*)&D[(size_t)(r0 + 8) * ldd + cb] = make_float2(c[mt][nt].z, c[mt][nt].w);
            if (X2) {
                if (r0 == cb)          X2[r0] = c[mt][nt].x;
                else if (r0 == cb + 1) X2[r0] = c[mt][nt].y;
                if (r0 + 8 == cb)          X2[r0 + 8] = c[mt][nt].z;
                else if (r0 + 8 == cb + 1) X2[r0 + 8] = c[mt][nt].w;
            }
        }
    }

    // ---- mirror for symmetric off-diagonal tiles ----
    if (SYMM && m0 != n0) {
        __syncthreads();
        float* st = (float*)smem;   // [64][65]
#pragma unroll
        for (int mt = 0; mt < MT; mt++) {
            int lm = wm + mt * 16 + lg;
#pragma unroll
            for (int nt = 0; nt < NTN; nt++) {
                int ln = wn + nt * 8 + lq * 2;
                st[lm * 65 + ln]           = c[mt][nt].x;
                st[lm * 65 + ln + 1]       = c[mt][nt].y;
                st[(lm + 8) * 65 + ln]     = c[mt][nt].z;
                st[(lm + 8) * 65 + ln + 1] = c[mt][nt].w;
            }
        }
        __syncthreads();
        const int rr = t >> 2, q = t & 3;
#pragma unroll
        for (int s = 0; s < 4; s++) {
            int cc = q * 16 + s * 4;
            float4 v = make_float4(st[(cc + 0) * 65 + rr], st[(cc + 1) * 65 + rr],
                                   st[(cc + 2) * 65 + rr], st[(cc + 3) * 65 + rr]);
            *(float4*)&D[(size_t)(n0 + rr) * ldd + m0 + cc] = v;
        }
    }
}

// ================= transpose x, eps; emit fp32 + fp16-split x =================
__global__ __launch_bounds__(256) void transpose_kernel(
    const float* __restrict__ x, const float* __restrict__ e,
    float* __restrict__ xT, float* __restrict__ eT,
    __half* __restrict__ xh, __half* __restrict__ xl) {
    __shared__ float tx[32][33], te[32][33];
    const int i0 = blockIdx.x * 32;   // N
    const int j0 = blockIdx.y * 32;   // C
    const int c = threadIdx.x, r = threadIdx.y;
#pragma unroll
    for (int k = 0; k < 32; k += 8) {
        tx[r + k][c] = x[(size_t)(j0 + r + k) * ND + i0 + c];
        te[r + k][c] = e[(size_t)(j0 + r + k) * ND + i0 + c];
    }
    __syncthreads();
#pragma unroll
    for (int k = 0; k < 32; k += 8) {
        size_t o = (size_t)(i0 + r + k) * CD + j0 + c;
        float v = tx[c][r + k];
        xT[o] = v;
        eT[o] = te[c][r + k];
        __half h, l;
        split_h(v, h, l);
        xh[o] = h;
        xl[o] = l;
    }
}

// ================= W -> fp16 (hi only; 1-pass out GEMM) =================
__global__ __launch_bounds__(256) void wsplit_kernel(const float* __restrict__ W,
                                                     __half* __restrict__ Wh) {
    int i = blockIdx.x * blockDim.x + threadIdx.x;   // over OD*CD/4
    float4 v = ((const float4*)W)[i];
    ((uint2*)Wh)[i] = make_uint2(
        pack2(__float2half_rn(v.x), __float2half_rn(v.y)),
        pack2(__float2half_rn(v.z), __float2half_rn(v.w)));
}

// ================= top-20: warp-per-row, smem dists + reg group-maxes =========
// Lane owns 8 groups of 4 (32 dists) stored in smem; per-group argmax in regs.
// Per extraction: 8-cmp reg scan + butterfly (tie -> lowest index) + owner's
// single-LDS repair. No block barriers, no register-array spills.
__global__ __launch_bounds__(128) void topk_kernel(const float* __restrict__ G,
                                                   const float* __restrict__ x2,
                                                   int* __restrict__ idx) {
    __shared__ float d[4][ND];
    const int t = threadIdx.x, wid = t >> 5, lane = t & 31;
    const int row = blockIdx.x * 4 + wid;
    const float x2i = x2[row];
    float* dr = d[wid];

    float mv[8];
    int   mi[8];
#pragma unroll
    for (int j = 0; j < 8; j++) {
        const int gi = j * 128 + lane * 4;
        float4 g = *(const float4*)&G[(size_t)row * ND + gi];
        float4 q = *(const float4*)&x2[gi];
        float v0 = 2.f * g.x - x2i - q.x;
        float v1 = 2.f * g.y - x2i - q.y;
        float v2 = 2.f * g.z - x2i - q.z;
        float v3 = 2.f * g.w - x2i - q.w;
        *(float4*)&dr[gi] = make_float4(v0, v1, v2, v3);
        float bv = v0; int bi = gi;
        if (v1 > bv) { bv = v1; bi = gi + 1; }
        if (v2 > bv) { bv = v2; bi = gi + 2; }
        if (v3 > bv) { bv = v3; bi = gi + 3; }
        mv[j] = bv; mi[j] = bi;
    }
    __syncwarp();

    for (int k = 0; k < KNN; k++) {
        float cv = mv[0]; int ci = mi[0];
#pragma unroll
        for (int j = 1; j < 8; j++)
            if (mv[j] > cv) { cv = mv[j]; ci = mi[j]; }   // ascending j => lowest idx on tie
#pragma unroll
        for (int off = 16; off > 0; off >>= 1) {
            float ov = __shfl_xor_sync(0xffffffffu, cv, off);
            int   oi = __shfl_xor_sync(0xffffffffu, ci, off);
            if (ov > cv || (ov == cv && oi < ci)) { cv = ov; ci = oi; }
        }
        if (lane == 0) idx[(size_t)row * KNN + k] = ci;
        if (lane == ((ci >> 2) & 31)) {
            dr[ci] = -CUDART_INF_F;
            const int jj = ci >> 7;
            const int gb = ci & ~3;
            float4 v = *(const float4*)&dr[gb];
            float bv = v.x; int bi = gb;
            if (v.y > bv) { bv = v.y; bi = gb + 1; }
            if (v.z > bv) { bv = v.z; bi = gb + 2; }
            if (v.w > bv) { bv = v.w; bi = gb + 3; }
#pragma unroll
            for (int j = 0; j < 8; j++)
                if (j == jj) { mv[j] = bv; mi[j] = bi; }
        }
        __syncwarp();
    }
}

// ====== h^T = (1+eps)*x + neighbor-sum, emitted fp16 (hi) =====================
__global__ __launch_bounds__(256) void hT_kernel(const float* __restrict__ xT,
                                                 const float* __restrict__ eT,
                                                 const int* __restrict__ idx,
                                                 __half* __restrict__ hh) {
    __shared__ int nb[KNN];
    const int n = blockIdx.x;
    const int t = threadIdx.x;
    if (t < KNN) nb[t] = idx[n * KNN + t];
    __syncthreads();

    const size_t base = (size_t)n * CD + t * 4;
    float4 xv = *(const float4*)&xT[base];
    float4 ev = *(const float4*)&eT[base];
    float4 s;
    s.x = fmaf(ev.x, xv.x, xv.x);
    s.y = fmaf(ev.y, xv.y, xv.y);
    s.z = fmaf(ev.z, xv.z, xv.z);
    s.w = fmaf(ev.w, xv.w, xv.w);
#pragma unroll
    for (int k = 0; k < KNN; k++) {
        float4 nv = *(const float4*)&xT[(size_t)nb[k] * CD + t * 4];
        s.x += nv.x; s.y += nv.y; s.z += nv.z; s.w += nv.w;
    }
    ((uint2*)hh)[base / 4] = make_uint2(
        pack2(__float2half_rn(s.x), __float2half_rn(s.y)),
        pack2(__float2half_rn(s.z), __float2half_rn(s.w)));
}

// ================= launch =================
extern "C" void kernel_launch(void* const* d_in, const int* in_sizes, int n_in,
                              void* d_out, int out_size) {
    const float* x   = (const float*)d_in[0];   // (C, N)
    const float* W   = (const float*)d_in[1];   // (O, C)
    const float* eps = (const float*)d_in[2];   // (C, N)
    float* out = (float*)d_out;                 // (O, N)

    float*  xT;   cudaGetSymbolAddress((void**)&xT,   g_xT);
    float*  eT;   cudaGetSymbolAddress((void**)&eT,   g_eT);
    __half* xh;   cudaGetSymbolAddress((void**)&xh,   g_xh);
    __half* xl;   cudaGetSymbolAddress((void**)&xl,   g_xl);
    __half* wh;   cudaGetSymbolAddress((void**)&wh,   g_wh);
    __half* hh;   cudaGetSymbolAddress((void**)&hh,   g_hh);
    float*  gram; cudaGetSymbolAddress((void**)&gram, g_gram);
    float*  x2;   cudaGetSymbolAddress((void**)&x2,   g_x2);
    int*    idx;  cudaGetSymbolAddress((void**)&idx,  g_idx);

    // gram: MTILE=64,NT=64,PASSES=3 -> stage 2*4096+2*4096 = 16384
    // out:  MTILE=128,NT=128,PASSES=1 -> stage 8192+8192 = 16384
    const int SMEM = 3 * 16384;   // 49152
    cudaFuncSetAttribute(mma_gemm<64, 64, 4, 3, true>,
                         cudaFuncAttributeMaxDynamicSharedMemorySize, SMEM);
    cudaFuncSetAttribute(mma_gemm<128, 128, 4, 1, false>,
                         cudaFuncAttributeMaxDynamicSharedMemorySize, SMEM);

    transpose_kernel<<<dim3(ND / 32, CD / 32), dim3(32, 8)>>>(x, eps, xT, eT, xh, xl);
    wsplit_kernel<<<(OD * CD / 4) / 256, 256>>>(W, wh);
    // Gram: symmetric upper-triangle 64x64 tiles: 136 CTAs, 3-pass, diag fused
    mma_gemm<64, 64, 4, 3, true><<<136, 256, SMEM>>>(xh, xl, xh, xl, gram, ND, x2);
    topk_kernel<<<ND / 4, 128>>>(gram, x2, idx);
    hT_kernel<<<ND, 256>>>(xT, eT, idx, hh);
    // Out: plain fp16 1-pass, CTA 128x128 -> 128 CTAs
    mma_gemm<128, 128, 4, 1, false><<<dim3(ND / 128, OD / 128), 256, SMEM>>>(
        wh, nullptr, hh, nullptr, out, ND, nullptr);
}